// round 4
// baseline (speedup 1.0000x reference)
#include <cuda_runtime.h>
#include <mma.h>
#include <math.h>

using namespace nvcuda;

#define TT 4096
#define DD 512
#define HH 2048
#define EE 8
#define CAP 1075          // round(2*4096*1.05/8)
#define CAPMAX 1088       // 17 * 64, padded row count per expert

// ---------------- static device scratch (no allocations allowed) ----------------
__device__ float g_imp[EE];                 // sum of gates per expert (router)
__device__ int   g_ti[2 * TT];              // top indices, slot-major: [slot*T + t]
__device__ float g_tg[2 * TT];              // top gate values, slot-major
__device__ int   g_cnt[EE];                 // post-capacity rows per expert
__device__ int   g_dtok[EE * CAPMAX];       // dispatch: token id
__device__ float g_dwt[EE * CAPMAX];        // dispatch: gate weight
__device__ int   g_dslot[EE * CAPMAX];      // dispatch: which k-slot
__device__ __align__(16) float g_hbuf[(size_t)EE * CAPMAX * HH];   // 71 MB intermediate
__device__ __align__(16) float g_part[(size_t)2 * TT * DD];        // 16 MB partial outputs (zero-init; never-dispatched slots stay 0)

// ---------------- kernel 0: zero router accumulators ----------------
__global__ void zero_imp_kernel() {
    if (threadIdx.x < EE) g_imp[threadIdx.x] = 0.f;
}

// ---------------- kernel 1: router (logits, softmax, top-2, imp) ----------------
// One warp per token; gate_w staged in SMEM.
__global__ void __launch_bounds__(256) router_kernel(const float* __restrict__ x,
                                                     const float* __restrict__ gw) {
    __shared__ float sgw[EE * DD];
    int tid = threadIdx.x;
    for (int i = tid; i < EE * DD / 4; i += 256)
        ((float4*)sgw)[i] = ((const float4*)gw)[i];
    __syncthreads();

    int wid = tid >> 5, lane = tid & 31;
    int t = blockIdx.x * 8 + wid;
    const float* xr = x + (size_t)t * DD;

    float acc[EE];
#pragma unroll
    for (int e = 0; e < EE; e++) acc[e] = 0.f;
#pragma unroll
    for (int i = 0; i < DD / 32; i++) {
        int d = lane + i * 32;
        float xv = xr[d];
#pragma unroll
        for (int e = 0; e < EE; e++) acc[e] = fmaf(xv, sgw[e * DD + d], acc[e]);
    }
#pragma unroll
    for (int e = 0; e < EE; e++) {
#pragma unroll
        for (int o = 16; o > 0; o >>= 1)
            acc[e] += __shfl_xor_sync(0xffffffffu, acc[e], o);
    }
    if (lane == 0) {
        float mx = acc[0];
#pragma unroll
        for (int e = 1; e < EE; e++) mx = fmaxf(mx, acc[e]);
        float g[EE], s = 0.f;
#pragma unroll
        for (int e = 0; e < EE; e++) { g[e] = expf(acc[e] - mx); s += g[e]; }
        float inv = 1.f / s;
#pragma unroll
        for (int e = 0; e < EE; e++) { g[e] *= inv; atomicAdd(&g_imp[e], g[e]); }
        // top-2, ties -> lower index (matches lax.top_k)
        int i0 = 0; float g0 = g[0];
#pragma unroll
        for (int e = 1; e < EE; e++) if (g[e] > g0) { g0 = g[e]; i0 = e; }
        int i1 = -1; float g1 = -1.f;
#pragma unroll
        for (int e = 0; e < EE; e++) if (e != i0 && g[e] > g1) { g1 = g[e]; i1 = e; }
        g_ti[t] = i0;        g_ti[TT + t] = i1;
        g_tg[t] = g0;        g_tg[TT + t] = g1;
    }
}

// ---------------- kernel 2: slot-major capacity scan + dispatch + losses ----------------
// Exact replication of: idx_sm = top_i.T.reshape(-1); pos = exclusive cumsum of same-expert;
// within = pos < CAP. Positions double as compaction indices into per-expert lists.
__global__ void __launch_bounds__(1024) scan_kernel(float* __restrict__ out, int out_size) {
    int i = threadIdx.x;                 // 1024 threads * 8 entries = 8192 entries
    int myexp[8];
    unsigned long long c0 = 0, c1 = 0;   // 4 experts x 16-bit counters per word
#pragma unroll
    for (int u = 0; u < 8; u++) {
        int j = i * 8 + u;
        int e = g_ti[j];
        myexp[u] = e;
        if (e < 4) c0 += 1ULL << (16 * e); else c1 += 1ULL << (16 * (e - 4));
    }
    __shared__ unsigned long long sA[1024], sB[1024];
    sA[i] = c0; sB[i] = c1;
    __syncthreads();
    for (int off = 1; off < 1024; off <<= 1) {
        unsigned long long a = 0, b = 0;
        if (i >= off) { a = sA[i - off]; b = sB[i - off]; }
        __syncthreads();
        sA[i] += a; sB[i] += b;
        __syncthreads();
    }
    unsigned long long e0 = sA[i] - c0, e1 = sB[i] - c1;   // exclusive prefix
    int run[8];
#pragma unroll
    for (int e = 0; e < 4; e++) {
        run[e]     = (int)((e0 >> (16 * e)) & 0xFFFF);
        run[e + 4] = (int)((e1 >> (16 * e)) & 0xFFFF);
    }
#pragma unroll
    for (int u = 0; u < 8; u++) {
        int j = i * 8 + u;
        int e = myexp[u];
        int pos = run[e]++;
        if (pos < CAP) {
            int o = e * CAPMAX + pos;
            g_dtok[o]  = j & (TT - 1);
            g_dwt[o]   = g_tg[j];
            g_dslot[o] = j >> 12;        // T == 4096 == 2^12
        }
    }
    if (i == 1023) {
        unsigned long long t0 = sA[1023], t1 = sB[1023];
        float tpe[8];
        for (int e = 0; e < 4; e++) {
            int a = min((int)((t0 >> (16 * e)) & 0xFFFF), CAP);
            int b = min((int)((t1 >> (16 * e)) & 0xFFFF), CAP);
            g_cnt[e] = a;     tpe[e] = (float)a;
            g_cnt[e + 4] = b; tpe[e + 4] = (float)b;
        }
        double s = 0, ss = 0;
        for (int e = 0; e < 8; e++) { s += tpe[e]; ss += (double)tpe[e] * tpe[e]; }
        double m = s / 8.0, var = ss / 8.0 - m * m; if (var < 0) var = 0;
        double l_load = var / ((m + 1e-6) * (m + 1e-6));
        double s2 = 0, sq2 = 0;
        for (int e = 0; e < 8; e++) { double v = g_imp[e]; s2 += v; sq2 += v * v; }
        double m2 = s2 / 8.0, v2 = sq2 / 8.0 - m2 * m2; if (v2 < 0) v2 = 0;
        double imp_loss = v2 / ((m2 + 1e-6) * (m2 + 1e-6));
        double l_aux = 0.5 * (imp_loss + l_load);
        if (out_size >= TT * DD + 2) {
            out[TT * DD]     = (float)l_aux;
            out[TT * DD + 1] = (float)l_load;
        }
    }
}

// ---------------- kernel 3: grouped GEMM1  Hbuf = gelu(Xg @ W1[e] + b1[e]) ----------------
// Block tile 64x64, k-slab 32, wmma tf32 16x16x8. 8 warps = 4(M) x 2(N), 2 n-frags each.
__global__ void __launch_bounds__(256) gemm1_kernel(const float* __restrict__ x,
                                                    const float* __restrict__ w1,
                                                    const float* __restrict__ b1) {
    int e = blockIdx.z;
    int rows = g_cnt[e];
    int row0 = blockIdx.x * 64;
    if (row0 >= rows) return;
    int h0 = blockIdx.y * 64;

    __shared__ __align__(16) float As[64][36];
    __shared__ __align__(16) float Bs[32][68];
    __shared__ __align__(16) float Cs[64][68];
    __shared__ int toks[64];

    int tid = threadIdx.x;
    if (tid < 64) {
        int r = row0 + tid;
        toks[tid] = (r < rows) ? g_dtok[e * CAPMAX + r] : -1;
    }
    __syncthreads();

    int wid = tid >> 5;
    int wm = wid & 3, wn = wid >> 2;

    wmma::fragment<wmma::accumulator, 16, 16, 8, float> acc[2];
    wmma::fill_fragment(acc[0], 0.f);
    wmma::fill_fragment(acc[1], 0.f);

    const float* w1e = w1 + (size_t)e * DD * HH;

    for (int k0 = 0; k0 < DD; k0 += 32) {
#pragma unroll
        for (int it = 0; it < 2; it++) {           // A: 64x32 = 512 float4
            int idx = tid + it * 256;
            int r = idx >> 3, c = idx & 7;
            int tok = toks[r];
            float4 v = make_float4(0.f, 0.f, 0.f, 0.f);
            if (tok >= 0) v = *(const float4*)(x + (size_t)tok * DD + k0 + c * 4);
            *(float4*)&As[r][c * 4] = v;
        }
#pragma unroll
        for (int it = 0; it < 2; it++) {           // B: 32x64 = 512 float4
            int idx = tid + it * 256;
            int kr = idx >> 4, c = idx & 15;
            float4 v = *(const float4*)(w1e + (size_t)(k0 + kr) * HH + h0 + c * 4);
            *(float4*)&Bs[kr][c * 4] = v;
        }
        __syncthreads();
#pragma unroll
        for (int kk = 0; kk < 4; kk++) {
            wmma::fragment<wmma::matrix_a, 16, 16, 8, wmma::precision::tf32, wmma::row_major> a;
            wmma::load_matrix_sync(a, &As[wm * 16][kk * 8], 36);
#pragma unroll
            for (int q = 0; q < a.num_elements; q++) a.x[q] = wmma::__float_to_tf32(a.x[q]);
#pragma unroll
            for (int nn = 0; nn < 2; nn++) {
                wmma::fragment<wmma::matrix_b, 16, 16, 8, wmma::precision::tf32, wmma::row_major> b;
                wmma::load_matrix_sync(b, &Bs[kk * 8][wn * 32 + nn * 16], 68);
#pragma unroll
                for (int q = 0; q < b.num_elements; q++) b.x[q] = wmma::__float_to_tf32(b.x[q]);
                wmma::mma_sync(acc[nn], a, b, acc[nn]);
            }
        }
        __syncthreads();
    }
    wmma::store_matrix_sync(&Cs[wm * 16][wn * 32],      acc[0], 68, wmma::mem_row_major);
    wmma::store_matrix_sync(&Cs[wm * 16][wn * 32 + 16], acc[1], 68, wmma::mem_row_major);
    __syncthreads();

    for (int idx = tid; idx < 64 * 64; idx += 256) {
        int r = idx >> 6, c = idx & 63;
        if (row0 + r < rows) {
            float v = Cs[r][c] + b1[e * HH + h0 + c];
            v = 0.5f * v * (1.f + erff(v * 0.7071067811865476f));   // exact GELU
            g_hbuf[((size_t)(e * CAPMAX) + row0 + r) * HH + h0 + c] = v;
        }
    }
}

// ---------------- kernel 4: grouped GEMM2  part[slot][tok] = wt * (Hbuf @ W2[e] + b2[e]) ----------------
__global__ void __launch_bounds__(256) gemm2_kernel(const float* __restrict__ w2,
                                                    const float* __restrict__ b2) {
    int e = blockIdx.z;
    int rows = g_cnt[e];
    int row0 = blockIdx.x * 64;
    if (row0 >= rows) return;
    int d0 = blockIdx.y * 64;

    __shared__ __align__(16) float As[64][36];
    __shared__ __align__(16) float Bs[32][68];
    __shared__ __align__(16) float Cs[64][68];
    __shared__ int   stok[64];
    __shared__ float swt[64];
    __shared__ int   sslot[64];

    int tid = threadIdx.x;
    if (tid < 64) {
        int r = row0 + tid;
        if (r < rows) {
            int o = e * CAPMAX + r;
            stok[tid] = g_dtok[o]; swt[tid] = g_dwt[o]; sslot[tid] = g_dslot[o];
        } else {
            stok[tid] = 0; swt[tid] = 0.f; sslot[tid] = 0;
        }
    }
    __syncthreads();

    int wid = tid >> 5;
    int wm = wid & 3, wn = wid >> 2;

    wmma::fragment<wmma::accumulator, 16, 16, 8, float> acc[2];
    wmma::fill_fragment(acc[0], 0.f);
    wmma::fill_fragment(acc[1], 0.f);

    const float* ae  = g_hbuf + (size_t)e * CAPMAX * HH;
    const float* w2e = w2 + (size_t)e * HH * DD;

    for (int k0 = 0; k0 < HH; k0 += 32) {
#pragma unroll
        for (int it = 0; it < 2; it++) {
            int idx = tid + it * 256;
            int r = idx >> 3, c = idx & 7;
            float4 v = make_float4(0.f, 0.f, 0.f, 0.f);
            if (row0 + r < rows)
                v = *(const float4*)(ae + (size_t)(row0 + r) * HH + k0 + c * 4);
            *(float4*)&As[r][c * 4] = v;
        }
#pragma unroll
        for (int it = 0; it < 2; it++) {
            int idx = tid + it * 256;
            int kr = idx >> 4, c = idx & 15;
            float4 v = *(const float4*)(w2e + (size_t)(k0 + kr) * DD + d0 + c * 4);
            *(float4*)&Bs[kr][c * 4] = v;
        }
        __syncthreads();
#pragma unroll
        for (int kk = 0; kk < 4; kk++) {
            wmma::fragment<wmma::matrix_a, 16, 16, 8, wmma::precision::tf32, wmma::row_major> a;
            wmma::load_matrix_sync(a, &As[wm * 16][kk * 8], 36);
#pragma unroll
            for (int q = 0; q < a.num_elements; q++) a.x[q] = wmma::__float_to_tf32(a.x[q]);
#pragma unroll
            for (int nn = 0; nn < 2; nn++) {
                wmma::fragment<wmma::matrix_b, 16, 16, 8, wmma::precision::tf32, wmma::row_major> b;
                wmma::load_matrix_sync(b, &Bs[kk * 8][wn * 32 + nn * 16], 68);
#pragma unroll
                for (int q = 0; q < b.num_elements; q++) b.x[q] = wmma::__float_to_tf32(b.x[q]);
                wmma::mma_sync(acc[nn], a, b, acc[nn]);
            }
        }
        __syncthreads();
    }
    wmma::store_matrix_sync(&Cs[wm * 16][wn * 32],      acc[0], 68, wmma::mem_row_major);
    wmma::store_matrix_sync(&Cs[wm * 16][wn * 32 + 16], acc[1], 68, wmma::mem_row_major);
    __syncthreads();

    for (int idx = tid; idx < 64 * 64; idx += 256) {
        int r = idx >> 6, c = idx & 63;
        if (row0 + r < rows) {
            float v = swt[r] * (Cs[r][c] + b2[e * DD + d0 + c]);
            g_part[(size_t)sslot[r] * (TT * DD) + (size_t)stok[r] * DD + d0 + c] = v;
        }
    }
}

// ---------------- kernel 5: combine two slots into final output ----------------
__global__ void combine_kernel(float* __restrict__ out) {
    int i = blockIdx.x * 256 + threadIdx.x;       // TT*DD/4 float4s
    float4 a = ((const float4*)g_part)[i];
    float4 b = ((const float4*)g_part)[i + (TT * DD / 4)];
    ((float4*)out)[i] = make_float4(a.x + b.x, a.y + b.y, a.z + b.z, a.w + b.w);
}

// ---------------- launch ----------------
extern "C" void kernel_launch(void* const* d_in, const int* in_sizes, int n_in,
                              void* d_out, int out_size) {
    const float* x  = (const float*)d_in[0];   // [B,S,D] = [T, 512]
    const float* gw = (const float*)d_in[1];   // [E, D]
    const float* w1 = (const float*)d_in[2];   // [E, D, H]
    const float* b1 = (const float*)d_in[3];   // [E, H]
    const float* w2 = (const float*)d_in[4];   // [E, H, D]
    const float* b2 = (const float*)d_in[5];   // [E, D]
    float* out = (float*)d_out;

    zero_imp_kernel<<<1, 32>>>();
    router_kernel<<<TT / 8, 256>>>(x, gw);
    scan_kernel<<<1, 1024>>>(out, out_size);
    gemm1_kernel<<<dim3(CAPMAX / 64, HH / 64, EE), 256>>>(x, w1, b1);
    gemm2_kernel<<<dim3(CAPMAX / 64, DD / 64, EE), 256>>>(w2, b2);
    combine_kernel<<<(TT * DD / 4) / 256, 256>>>(out);
}

// round 5
// speedup vs baseline: 1.0819x; 1.0819x over previous
#include <cuda_runtime.h>
#include <mma.h>
#include <math.h>

using namespace nvcuda;

#define TT 4096
#define DD 512
#define HH 2048
#define EE 8
#define CAP 1075          // round(2*4096*1.05/8)
#define CAPMAX 1152       // 9 * 128, padded row count per expert

// ---------------- static device scratch ----------------
__device__ float g_imp[EE];
__device__ int   g_ti[2 * TT];              // top indices, slot-major
__device__ float g_tg[2 * TT];              // top gate values, slot-major
__device__ int   g_cnt[EE];                 // post-capacity rows per expert
__device__ int   g_dtok[EE * CAPMAX];       // dispatch: token id
__device__ float g_dwt[EE * CAPMAX];        // dispatch: gate weight
__device__ int   g_inv[2 * TT];             // (slot,token) -> e*CAPMAX+pos or -1
__device__ __align__(16) float g_hbuf[(size_t)EE * CAPMAX * HH];   // 75.5 MB
__device__ __align__(16) float g_ybuf[(size_t)EE * CAPMAX * DD];   // 18.9 MB

__device__ __forceinline__ float to_tf32(float x) {
    float r; asm("cvt.rna.tf32.f32 %0, %1;" : "=f"(r) : "f"(x)); return r;
}
__device__ __forceinline__ float4 cvt4(float4 v) {
    return make_float4(to_tf32(v.x), to_tf32(v.y), to_tf32(v.z), to_tf32(v.w));
}
__device__ __forceinline__ float4 cvt4s(float4 v, float s) {
    return make_float4(to_tf32(v.x * s), to_tf32(v.y * s), to_tf32(v.z * s), to_tf32(v.w * s));
}

// ---------------- kernel 0: zero router accumulators ----------------
__global__ void zero_imp_kernel() {
    if (threadIdx.x < EE) g_imp[threadIdx.x] = 0.f;
}

// ---------------- kernel 1: router ----------------
__global__ void __launch_bounds__(256) router_kernel(const float* __restrict__ x,
                                                     const float* __restrict__ gw) {
    __shared__ float sgw[EE * DD];
    int tid = threadIdx.x;
    for (int i = tid; i < EE * DD / 4; i += 256)
        ((float4*)sgw)[i] = ((const float4*)gw)[i];
    __syncthreads();

    int wid = tid >> 5, lane = tid & 31;
    int t = blockIdx.x * 8 + wid;
    const float* xr = x + (size_t)t * DD;

    float acc[EE];
#pragma unroll
    for (int e = 0; e < EE; e++) acc[e] = 0.f;
#pragma unroll
    for (int i = 0; i < DD / 32; i++) {
        int d = lane + i * 32;
        float xv = xr[d];
#pragma unroll
        for (int e = 0; e < EE; e++) acc[e] = fmaf(xv, sgw[e * DD + d], acc[e]);
    }
#pragma unroll
    for (int e = 0; e < EE; e++) {
#pragma unroll
        for (int o = 16; o > 0; o >>= 1)
            acc[e] += __shfl_xor_sync(0xffffffffu, acc[e], o);
    }
    if (lane == 0) {
        float mx = acc[0];
#pragma unroll
        for (int e = 1; e < EE; e++) mx = fmaxf(mx, acc[e]);
        float g[EE], s = 0.f;
#pragma unroll
        for (int e = 0; e < EE; e++) { g[e] = expf(acc[e] - mx); s += g[e]; }
        float inv = 1.f / s;
#pragma unroll
        for (int e = 0; e < EE; e++) { g[e] *= inv; atomicAdd(&g_imp[e], g[e]); }
        int i0 = 0; float g0 = g[0];
#pragma unroll
        for (int e = 1; e < EE; e++) if (g[e] > g0) { g0 = g[e]; i0 = e; }
        int i1 = -1; float g1 = -1.f;
#pragma unroll
        for (int e = 0; e < EE; e++) if (e != i0 && g[e] > g1) { g1 = g[e]; i1 = e; }
        g_ti[t] = i0;        g_ti[TT + t] = i1;
        g_tg[t] = g0;        g_tg[TT + t] = g1;
    }
}

// ---------------- kernel 2: slot-major capacity scan + dispatch + losses ----------------
__global__ void __launch_bounds__(1024) scan_kernel(float* __restrict__ out, int out_size) {
    int i = threadIdx.x;
    int myexp[8];
    unsigned long long c0 = 0, c1 = 0;
#pragma unroll
    for (int u = 0; u < 8; u++) {
        int j = i * 8 + u;
        int e = g_ti[j];
        myexp[u] = e;
        if (e < 4) c0 += 1ULL << (16 * e); else c1 += 1ULL << (16 * (e - 4));
    }
    __shared__ unsigned long long sA[1024], sB[1024];
    sA[i] = c0; sB[i] = c1;
    __syncthreads();
    for (int off = 1; off < 1024; off <<= 1) {
        unsigned long long a = 0, b = 0;
        if (i >= off) { a = sA[i - off]; b = sB[i - off]; }
        __syncthreads();
        sA[i] += a; sB[i] += b;
        __syncthreads();
    }
    unsigned long long e0 = sA[i] - c0, e1 = sB[i] - c1;
    int run[8];
#pragma unroll
    for (int e = 0; e < 4; e++) {
        run[e]     = (int)((e0 >> (16 * e)) & 0xFFFF);
        run[e + 4] = (int)((e1 >> (16 * e)) & 0xFFFF);
    }
#pragma unroll
    for (int u = 0; u < 8; u++) {
        int j = i * 8 + u;
        int e = myexp[u];
        int pos = run[e]++;
        if (pos < CAP) {
            int o = e * CAPMAX + pos;
            g_dtok[o] = j & (TT - 1);
            g_dwt[o]  = g_tg[j];
            g_inv[j]  = o;
        } else {
            g_inv[j] = -1;
        }
    }
    if (i == 1023) {
        unsigned long long t0 = sA[1023], t1 = sB[1023];
        float tpe[8];
        for (int e = 0; e < 4; e++) {
            int a = min((int)((t0 >> (16 * e)) & 0xFFFF), CAP);
            int b = min((int)((t1 >> (16 * e)) & 0xFFFF), CAP);
            g_cnt[e] = a;     tpe[e] = (float)a;
            g_cnt[e + 4] = b; tpe[e + 4] = (float)b;
        }
        double s = 0, ss = 0;
        for (int e = 0; e < 8; e++) { s += tpe[e]; ss += (double)tpe[e] * tpe[e]; }
        double m = s / 8.0, var = ss / 8.0 - m * m; if (var < 0) var = 0;
        double l_load = var / ((m + 1e-6) * (m + 1e-6));
        double s2 = 0, sq2 = 0;
        for (int e = 0; e < 8; e++) { double v = g_imp[e]; s2 += v; sq2 += v * v; }
        double m2 = s2 / 8.0, v2 = sq2 / 8.0 - m2 * m2; if (v2 < 0) v2 = 0;
        double imp_loss = v2 / ((m2 + 1e-6) * (m2 + 1e-6));
        if (out_size >= TT * DD + 2) {
            out[TT * DD]     = (float)(0.5 * (imp_loss + l_load));
            out[TT * DD + 1] = (float)l_load;
        }
    }
}

// ---------------- kernel 3: GEMM1  hbuf = gelu(Xg @ W1[e] + b1[e]) ----------------
// Block tile 128x64, k-slab 32, double-buffered SMEM, register prefetch, tf32 wmma.
// smem floats: As[2][128][36] @0 (9216) | Bs[2][32][68] @9216 (4352) | bias[16][68] @13568 (1088) | toks[128] @14656
#define G1_SMEM_BYTES (14784 * 4)
__global__ void __launch_bounds__(256, 2) gemm1_kernel(const float* __restrict__ x,
                                                       const float* __restrict__ w1,
                                                       const float* __restrict__ b1) {
    extern __shared__ float sm[];
    float (*As)[128][36] = (float (*)[128][36])sm;
    float (*Bs)[32][68]  = (float (*)[32][68])(sm + 9216);
    float (*bias_s)[68]  = (float (*)[68])(sm + 13568);
    int* toks = (int*)(sm + 14656);

    int e = blockIdx.z;
    int rows = g_cnt[e];
    int row0 = blockIdx.x * 128;
    if (row0 >= rows) return;
    int h0 = blockIdx.y * 64;

    int tid = threadIdx.x;
    if (tid < 128) {
        int r = row0 + tid;
        toks[tid] = (r < rows) ? g_dtok[e * CAPMAX + r] : -1;
    }
#pragma unroll
    for (int it = 0; it < 4; it++) {
        int idx = tid + it * 256;
        bias_s[idx >> 6][idx & 63] = b1[e * HH + h0 + (idx & 63)];
    }
    __syncthreads();

    const float* w1e = w1 + (size_t)e * DD * HH;
    float4 ra[4], rb[2];

    // ---- stage slab 0 ----
#pragma unroll
    for (int it = 0; it < 4; it++) {
        int idx = tid + it * 256; int r = idx >> 3, c = idx & 7;
        int tok = toks[r];
        ra[it] = (tok >= 0) ? *(const float4*)(x + (size_t)tok * DD + c * 4)
                            : make_float4(0.f, 0.f, 0.f, 0.f);
    }
#pragma unroll
    for (int it = 0; it < 2; it++) {
        int idx = tid + it * 256; int kr = idx >> 4, c = idx & 15;
        rb[it] = *(const float4*)(w1e + (size_t)kr * HH + h0 + c * 4);
    }
#pragma unroll
    for (int it = 0; it < 4; it++) {
        int idx = tid + it * 256; int r = idx >> 3, c = idx & 7;
        *(float4*)&As[0][r][c * 4] = cvt4(ra[it]);
    }
#pragma unroll
    for (int it = 0; it < 2; it++) {
        int idx = tid + it * 256; int kr = idx >> 4, c = idx & 15;
        *(float4*)&Bs[0][kr][c * 4] = cvt4(rb[it]);
    }
    __syncthreads();

    int wid = tid >> 5, wm = wid & 3, wn = wid >> 2;
    wmma::fragment<wmma::accumulator, 16, 16, 8, float> acc[2][2];
#pragma unroll
    for (int mi = 0; mi < 2; mi++)
#pragma unroll
        for (int ni = 0; ni < 2; ni++)
            wmma::load_matrix_sync(acc[mi][ni], &bias_s[0][wn * 32 + ni * 16], 68,
                                   wmma::mem_row_major);

    for (int ks = 0; ks < 16; ks++) {
        int cur = ks & 1;
        if (ks < 15) {
            int k0 = (ks + 1) * 32;
#pragma unroll
            for (int it = 0; it < 4; it++) {
                int idx = tid + it * 256; int r = idx >> 3, c = idx & 7;
                int tok = toks[r];
                ra[it] = (tok >= 0) ? *(const float4*)(x + (size_t)tok * DD + k0 + c * 4)
                                    : make_float4(0.f, 0.f, 0.f, 0.f);
            }
#pragma unroll
            for (int it = 0; it < 2; it++) {
                int idx = tid + it * 256; int kr = idx >> 4, c = idx & 15;
                rb[it] = *(const float4*)(w1e + (size_t)(k0 + kr) * HH + h0 + c * 4);
            }
        }
#pragma unroll
        for (int kk = 0; kk < 4; kk++) {
            wmma::fragment<wmma::matrix_a, 16, 16, 8, wmma::precision::tf32, wmma::row_major> a[2];
            wmma::fragment<wmma::matrix_b, 16, 16, 8, wmma::precision::tf32, wmma::row_major> b[2];
            wmma::load_matrix_sync(a[0], &As[cur][wm * 32][kk * 8], 36);
            wmma::load_matrix_sync(a[1], &As[cur][wm * 32 + 16][kk * 8], 36);
            wmma::load_matrix_sync(b[0], &Bs[cur][kk * 8][wn * 32], 68);
            wmma::load_matrix_sync(b[1], &Bs[cur][kk * 8][wn * 32 + 16], 68);
#pragma unroll
            for (int mi = 0; mi < 2; mi++)
#pragma unroll
                for (int ni = 0; ni < 2; ni++)
                    wmma::mma_sync(acc[mi][ni], a[mi], b[ni], acc[mi][ni]);
        }
        if (ks < 15) {
            int nb = cur ^ 1;
#pragma unroll
            for (int it = 0; it < 4; it++) {
                int idx = tid + it * 256; int r = idx >> 3, c = idx & 7;
                *(float4*)&As[nb][r][c * 4] = cvt4(ra[it]);
            }
#pragma unroll
            for (int it = 0; it < 2; it++) {
                int idx = tid + it * 256; int kr = idx >> 4, c = idx & 15;
                *(float4*)&Bs[nb][kr][c * 4] = cvt4(rb[it]);
            }
        }
        __syncthreads();
    }

    float* hb = g_hbuf + (size_t)(e * CAPMAX + row0 + wm * 32) * HH + h0 + wn * 32;
#pragma unroll
    for (int mi = 0; mi < 2; mi++)
#pragma unroll
        for (int ni = 0; ni < 2; ni++) {
#pragma unroll
            for (int q = 0; q < 8; q++) {
                float v = acc[mi][ni].x[q];
                acc[mi][ni].x[q] = 0.5f * v * (1.f + erff(v * 0.7071067811865476f));
            }
            wmma::store_matrix_sync(hb + (size_t)mi * 16 * HH + ni * 16, acc[mi][ni], HH,
                                    wmma::mem_row_major);
        }
}

// ---------------- kernel 4: GEMM2  ybuf = (wt*hbuf) @ W2[e] + wt*b2 (rank-1 slab) ----------------
// smem floats: As[2][128][36] @0 | Bs[2][32][68] @9216 | swt[128] @13568
#define G2_SMEM_BYTES (13696 * 4)
__global__ void __launch_bounds__(256, 2) gemm2_kernel(const float* __restrict__ w2,
                                                       const float* __restrict__ b2) {
    extern __shared__ float sm[];
    float (*As)[128][36] = (float (*)[128][36])sm;
    float (*Bs)[32][68]  = (float (*)[32][68])(sm + 9216);
    float* swt = sm + 13568;

    int e = blockIdx.z;
    int rows = g_cnt[e];
    int row0 = blockIdx.x * 128;
    if (row0 >= rows) return;
    int d0 = blockIdx.y * 64;

    int tid = threadIdx.x;
    if (tid < 128) {
        int r = row0 + tid;
        swt[tid] = (r < rows) ? g_dwt[e * CAPMAX + r] : 0.f;
    }
    __syncthreads();

    const float* hbase = g_hbuf + (size_t)(e * CAPMAX + row0) * HH;
    const float* w2e = w2 + (size_t)e * HH * DD;
    const float* b2e = b2 + e * DD + d0;
    float4 ra[4], rb[2];

    // ---- stage slab 0 ----
#pragma unroll
    for (int it = 0; it < 4; it++) {
        int idx = tid + it * 256; int r = idx >> 3, c = idx & 7;
        ra[it] = *(const float4*)(hbase + (size_t)r * HH + c * 4);
    }
#pragma unroll
    for (int it = 0; it < 2; it++) {
        int idx = tid + it * 256; int kr = idx >> 4, c = idx & 15;
        rb[it] = *(const float4*)(w2e + (size_t)kr * DD + d0 + c * 4);
    }
#pragma unroll
    for (int it = 0; it < 4; it++) {
        int idx = tid + it * 256; int r = idx >> 3, c = idx & 7;
        *(float4*)&As[0][r][c * 4] = cvt4s(ra[it], swt[r]);
    }
#pragma unroll
    for (int it = 0; it < 2; it++) {
        int idx = tid + it * 256; int kr = idx >> 4, c = idx & 15;
        *(float4*)&Bs[0][kr][c * 4] = cvt4(rb[it]);
    }
    __syncthreads();

    int wid = tid >> 5, wm = wid & 3, wn = wid >> 2;
    wmma::fragment<wmma::accumulator, 16, 16, 8, float> acc[2][2];
#pragma unroll
    for (int mi = 0; mi < 2; mi++)
#pragma unroll
        for (int ni = 0; ni < 2; ni++)
            wmma::fill_fragment(acc[mi][ni], 0.f);

    // 64 real slabs + 1 rank-1 bias slab (A=1 in col 0 -> wt after scaling; B row 0 = b2)
    for (int ks = 0; ks < 65; ks++) {
        int cur = ks & 1;
        if (ks < 64) {
            int s = ks + 1;
            if (s < 64) {
                int k0 = s * 32;
#pragma unroll
                for (int it = 0; it < 4; it++) {
                    int idx = tid + it * 256; int r = idx >> 3, c = idx & 7;
                    ra[it] = *(const float4*)(hbase + (size_t)r * HH + k0 + c * 4);
                }
#pragma unroll
                for (int it = 0; it < 2; it++) {
                    int idx = tid + it * 256; int kr = idx >> 4, c = idx & 15;
                    rb[it] = *(const float4*)(w2e + (size_t)(k0 + kr) * DD + d0 + c * 4);
                }
            } else {  // special bias slab
#pragma unroll
                for (int it = 0; it < 4; it++) {
                    int idx = tid + it * 256; int c = idx & 7;
                    ra[it] = (c == 0) ? make_float4(1.f, 0.f, 0.f, 0.f)
                                      : make_float4(0.f, 0.f, 0.f, 0.f);
                }
#pragma unroll
                for (int it = 0; it < 2; it++) {
                    int idx = tid + it * 256; int kr = idx >> 4, c = idx & 15;
                    rb[it] = (kr == 0) ? *(const float4*)(b2e + c * 4)
                                       : make_float4(0.f, 0.f, 0.f, 0.f);
                }
            }
        }
#pragma unroll
        for (int kk = 0; kk < 4; kk++) {
            wmma::fragment<wmma::matrix_a, 16, 16, 8, wmma::precision::tf32, wmma::row_major> a[2];
            wmma::fragment<wmma::matrix_b, 16, 16, 8, wmma::precision::tf32, wmma::row_major> b[2];
            wmma::load_matrix_sync(a[0], &As[cur][wm * 32][kk * 8], 36);
            wmma::load_matrix_sync(a[1], &As[cur][wm * 32 + 16][kk * 8], 36);
            wmma::load_matrix_sync(b[0], &Bs[cur][kk * 8][wn * 32], 68);
            wmma::load_matrix_sync(b[1], &Bs[cur][kk * 8][wn * 32 + 16], 68);
#pragma unroll
            for (int mi = 0; mi < 2; mi++)
#pragma unroll
                for (int ni = 0; ni < 2; ni++)
                    wmma::mma_sync(acc[mi][ni], a[mi], b[ni], acc[mi][ni]);
        }
        if (ks < 64) {
            int nb = cur ^ 1;
#pragma unroll
            for (int it = 0; it < 4; it++) {
                int idx = tid + it * 256; int r = idx >> 3, c = idx & 7;
                *(float4*)&As[nb][r][c * 4] = cvt4s(ra[it], swt[r]);
            }
#pragma unroll
            for (int it = 0; it < 2; it++) {
                int idx = tid + it * 256; int kr = idx >> 4, c = idx & 15;
                *(float4*)&Bs[nb][kr][c * 4] = cvt4(rb[it]);
            }
        }
        __syncthreads();
    }

    float* yb = g_ybuf + (size_t)(e * CAPMAX + row0 + wm * 32) * DD + d0 + wn * 32;
#pragma unroll
    for (int mi = 0; mi < 2; mi++)
#pragma unroll
        for (int ni = 0; ni < 2; ni++)
            wmma::store_matrix_sync(yb + (size_t)mi * 16 * DD + ni * 16, acc[mi][ni], DD,
                                    wmma::mem_row_major);
}

// ---------------- kernel 5: gather-combine two slots ----------------
__global__ void __launch_bounds__(256) combine_kernel(float* __restrict__ out) {
    int i = blockIdx.x * 256 + threadIdx.x;      // over TT*DD/4 float4s
    int t = i >> 7;                               // DD/4 = 128
    int d = i & 127;
    int i0 = g_inv[t], i1 = g_inv[TT + t];
    float4 a = make_float4(0.f, 0.f, 0.f, 0.f), b = a;
    if (i0 >= 0) a = *((const float4*)g_ybuf + (size_t)i0 * 128 + d);
    if (i1 >= 0) b = *((const float4*)g_ybuf + (size_t)i1 * 128 + d);
    ((float4*)out)[i] = make_float4(a.x + b.x, a.y + b.y, a.z + b.z, a.w + b.w);
}

// ---------------- launch ----------------
extern "C" void kernel_launch(void* const* d_in, const int* in_sizes, int n_in,
                              void* d_out, int out_size) {
    const float* x  = (const float*)d_in[0];
    const float* gw = (const float*)d_in[1];
    const float* w1 = (const float*)d_in[2];
    const float* b1 = (const float*)d_in[3];
    const float* w2 = (const float*)d_in[4];
    const float* b2 = (const float*)d_in[5];
    float* out = (float*)d_out;

    cudaFuncSetAttribute(gemm1_kernel, cudaFuncAttributeMaxDynamicSharedMemorySize, G1_SMEM_BYTES);
    cudaFuncSetAttribute(gemm2_kernel, cudaFuncAttributeMaxDynamicSharedMemorySize, G2_SMEM_BYTES);

    zero_imp_kernel<<<1, 32>>>();
    router_kernel<<<TT / 8, 256>>>(x, gw);
    scan_kernel<<<1, 1024>>>(out, out_size);
    gemm1_kernel<<<dim3(CAPMAX / 128, HH / 64, EE), 256, G1_SMEM_BYTES>>>(x, w1, b1);
    gemm2_kernel<<<dim3(CAPMAX / 128, DD / 64, EE), 256, G2_SMEM_BYTES>>>(w2, b2);
    combine_kernel<<<(TT * DD / 4) / 256, 256>>>(out);
}

// round 7
// speedup vs baseline: 1.2095x; 1.1180x over previous
#include <cuda_runtime.h>
#include <cstdint>
#include <mma.h>
#include <math.h>

using namespace nvcuda;

#define TT 4096
#define DD 512
#define HH 2048
#define EE 8
#define CAP 1075          // round(2*4096*1.05/8)
#define CAPMAX 1152       // 9 * 128

// ---------------- static device scratch ----------------
__device__ float g_imp[EE];
__device__ int   g_ti[2 * TT];
__device__ float g_tg[2 * TT];
__device__ int   g_cnt[EE];
__device__ int   g_dtok[EE * CAPMAX];
__device__ float g_dwt[EE * CAPMAX];
__device__ int   g_inv[2 * TT];
__device__ __align__(16) float g_xt [(size_t)TT * DD];            // tf32 x
__device__ __align__(16) float g_w1t[(size_t)EE * DD * HH];       // tf32 W1
__device__ __align__(16) float g_w2t[(size_t)EE * HH * DD];       // tf32 W2
__device__ __align__(16) float g_hbuf[(size_t)EE * CAPMAX * HH];  // tf32, gate-scaled gelu(h)
__device__ __align__(16) float g_ybuf[(size_t)EE * CAPMAX * DD];

__device__ __forceinline__ float to_tf32(float x) {
    float r; asm("cvt.rna.tf32.f32 %0, %1;" : "=f"(r) : "f"(x)); return r;
}
__device__ __forceinline__ float4 cvt4(float4 v) {
    return make_float4(to_tf32(v.x), to_tf32(v.y), to_tf32(v.z), to_tf32(v.w));
}
__device__ __forceinline__ void cp16(unsigned int dst, const float* src, int sz) {
    asm volatile("cp.async.cg.shared.global [%0], [%1], 16, %2;"
                 :: "r"(dst), "l"(src), "r"(sz));
}
__device__ __forceinline__ void cp_commit() { asm volatile("cp.async.commit_group;"); }
template<int N> __device__ __forceinline__ void cp_wait() {
    asm volatile("cp.async.wait_group %0;" :: "n"(N));
}

// ---------------- tf32 pre-convert kernels ----------------
__global__ void cvt_x_kernel(const float4* __restrict__ s) {
    int i = blockIdx.x * 256 + threadIdx.x;
    ((float4*)g_xt)[i] = cvt4(s[i]);
}
__global__ void cvt_w1_kernel(const float4* __restrict__ s) {
    int i = blockIdx.x * 256 + threadIdx.x;
    ((float4*)g_w1t)[i] = cvt4(s[i]);
}
__global__ void cvt_w2_kernel(const float4* __restrict__ s) {
    int i = blockIdx.x * 256 + threadIdx.x;
    ((float4*)g_w2t)[i] = cvt4(s[i]);
}

// ---------------- kernel 0 ----------------
__global__ void zero_imp_kernel() {
    if (threadIdx.x < EE) g_imp[threadIdx.x] = 0.f;
}

// ---------------- kernel 1: router ----------------
__global__ void __launch_bounds__(256) router_kernel(const float* __restrict__ x,
                                                     const float* __restrict__ gw) {
    __shared__ float sgw[EE * DD];
    int tid = threadIdx.x;
    for (int i = tid; i < EE * DD / 4; i += 256)
        ((float4*)sgw)[i] = ((const float4*)gw)[i];
    __syncthreads();

    int wid = tid >> 5, lane = tid & 31;
    int t = blockIdx.x * 8 + wid;
    const float* xr = x + (size_t)t * DD;

    float acc[EE];
#pragma unroll
    for (int e = 0; e < EE; e++) acc[e] = 0.f;
#pragma unroll
    for (int i = 0; i < DD / 32; i++) {
        int d = lane + i * 32;
        float xv = xr[d];
#pragma unroll
        for (int e = 0; e < EE; e++) acc[e] = fmaf(xv, sgw[e * DD + d], acc[e]);
    }
#pragma unroll
    for (int e = 0; e < EE; e++) {
#pragma unroll
        for (int o = 16; o > 0; o >>= 1)
            acc[e] += __shfl_xor_sync(0xffffffffu, acc[e], o);
    }
    if (lane == 0) {
        float mx = acc[0];
#pragma unroll
        for (int e = 1; e < EE; e++) mx = fmaxf(mx, acc[e]);
        float g[EE], s = 0.f;
#pragma unroll
        for (int e = 0; e < EE; e++) { g[e] = expf(acc[e] - mx); s += g[e]; }
        float inv = 1.f / s;
#pragma unroll
        for (int e = 0; e < EE; e++) { g[e] *= inv; atomicAdd(&g_imp[e], g[e]); }
        int i0 = 0; float g0 = g[0];
#pragma unroll
        for (int e = 1; e < EE; e++) if (g[e] > g0) { g0 = g[e]; i0 = e; }
        int i1 = -1; float g1 = -1.f;
#pragma unroll
        for (int e = 0; e < EE; e++) if (e != i0 && g[e] > g1) { g1 = g[e]; i1 = e; }
        g_ti[t] = i0;        g_ti[TT + t] = i1;
        g_tg[t] = g0;        g_tg[TT + t] = g1;
    }
}

// ---------------- kernel 2: slot-major capacity scan + losses ----------------
__global__ void __launch_bounds__(1024) scan_kernel(float* __restrict__ out, int out_size) {
    int i = threadIdx.x;
    int myexp[8];
    unsigned long long c0 = 0, c1 = 0;
#pragma unroll
    for (int u = 0; u < 8; u++) {
        int j = i * 8 + u;
        int e = g_ti[j];
        myexp[u] = e;
        if (e < 4) c0 += 1ULL << (16 * e); else c1 += 1ULL << (16 * (e - 4));
    }
    __shared__ unsigned long long sA[1024], sB[1024];
    sA[i] = c0; sB[i] = c1;
    __syncthreads();
    for (int off = 1; off < 1024; off <<= 1) {
        unsigned long long a = 0, b = 0;
        if (i >= off) { a = sA[i - off]; b = sB[i - off]; }
        __syncthreads();
        sA[i] += a; sB[i] += b;
        __syncthreads();
    }
    unsigned long long e0 = sA[i] - c0, e1 = sB[i] - c1;
    int run[8];
#pragma unroll
    for (int e = 0; e < 4; e++) {
        run[e]     = (int)((e0 >> (16 * e)) & 0xFFFF);
        run[e + 4] = (int)((e1 >> (16 * e)) & 0xFFFF);
    }
#pragma unroll
    for (int u = 0; u < 8; u++) {
        int j = i * 8 + u;
        int e = myexp[u];
        int pos = run[e]++;
        if (pos < CAP) {
            int o = e * CAPMAX + pos;
            g_dtok[o] = j & (TT - 1);
            g_dwt[o]  = g_tg[j];
            g_inv[j]  = o;
        } else {
            g_inv[j] = -1;
        }
    }
    if (i == 1023) {
        unsigned long long t0 = sA[1023], t1 = sB[1023];
        float tpe[8];
        for (int e = 0; e < 4; e++) {
            int a = min((int)((t0 >> (16 * e)) & 0xFFFF), CAP);
            int b = min((int)((t1 >> (16 * e)) & 0xFFFF), CAP);
            g_cnt[e] = a;     tpe[e] = (float)a;
            g_cnt[e + 4] = b; tpe[e + 4] = (float)b;
        }
        double s = 0, ss = 0;
        for (int e = 0; e < 8; e++) { s += tpe[e]; ss += (double)tpe[e] * tpe[e]; }
        double m = s / 8.0, var = ss / 8.0 - m * m; if (var < 0) var = 0;
        double l_load = var / ((m + 1e-6) * (m + 1e-6));
        double s2 = 0, sq2 = 0;
        for (int e = 0; e < 8; e++) { double v = g_imp[e]; s2 += v; sq2 += v * v; }
        double m2 = s2 / 8.0, v2 = sq2 / 8.0 - m2 * m2; if (v2 < 0) v2 = 0;
        double imp_loss = v2 / ((m2 + 1e-6) * (m2 + 1e-6));
        if (out_size >= TT * DD + 2) {
            out[TT * DD]     = (float)(0.5 * (imp_loss + l_load));
            out[TT * DD + 1] = (float)l_load;
        }
    }
}

// ============ GEMM tiling constants ============
// Block tile 128x128, k-slab 16, 4-stage cp.async.
// SMEM floats per stage: A [128][20] = 2560, B [16][136] = 2176  -> 4736
#define STG 4736
#define A_LD 20
#define B_LD 136
#define G1_SMEM ((4 * STG + 384) * 4)
#define G2_SMEM ((4 * STG) * 4)

// ---------------- kernel 3: GEMM1  hbuf = wt * gelu(Xg @ W1[e] + b1[e]) (tf32 out) ----------------
__global__ void __launch_bounds__(256, 2) gemm1_kernel(const float* __restrict__ b1) {
    extern __shared__ float sm[];
    unsigned int smb = (unsigned int)__cvta_generic_to_shared(sm);
    float* b1s = sm + 4 * STG;
    float* swt = sm + 4 * STG + 128;
    int*  toks = (int*)(sm + 4 * STG + 256);

    int e = blockIdx.z;
    int rows = g_cnt[e];
    int row0 = blockIdx.x * 128;
    if (row0 >= rows) return;
    int h0 = blockIdx.y * 128;

    int tid = threadIdx.x;
    if (tid < 128) {
        int r = row0 + tid;
        toks[tid] = (r < rows) ? g_dtok[e * CAPMAX + r] : -1;
        swt[tid]  = (r < rows) ? g_dwt[e * CAPMAX + r] : 0.f;
        b1s[tid]  = b1[e * HH + h0 + tid];
    }
    __syncthreads();

    const float* w1e = g_w1t + (size_t)e * DD * HH;

    auto issue = [&](int s, int b) {
        int k0 = s * 16;
        unsigned int Ad = smb + (unsigned int)(b * STG) * 4u;
        unsigned int Bd = Ad + 2560u * 4u;
#pragma unroll
        for (int it = 0; it < 2; it++) {
            int idx = tid + it * 256;        // A: 128 rows x 4 float4
            int r = idx >> 2, c = idx & 3;
            int tok = toks[r];
            const float* src = g_xt + (size_t)(tok < 0 ? 0 : tok) * DD + k0 + c * 4;
            cp16(Ad + (unsigned int)(r * A_LD + c * 4) * 4u, src, tok < 0 ? 0 : 16);
        }
#pragma unroll
        for (int it = 0; it < 2; it++) {
            int idx = tid + it * 256;        // B: 16 rows x 32 float4
            int kr = idx >> 5, c = idx & 31;
            cp16(Bd + (unsigned int)(kr * B_LD + c * 4) * 4u,
                 w1e + (size_t)(k0 + kr) * HH + h0 + c * 4, 16);
        }
    };

    issue(0, 0); cp_commit();
    issue(1, 1); cp_commit();
    issue(2, 2); cp_commit();

    int wid = tid >> 5, wm = wid & 3, wn = wid >> 2;   // warp tile 32(M) x 64(N)
    wmma::fragment<wmma::accumulator, 16, 16, 8, float> acc[2][4];
#pragma unroll
    for (int mi = 0; mi < 2; mi++)
#pragma unroll
        for (int ni = 0; ni < 4; ni++) wmma::fill_fragment(acc[mi][ni], 0.f);

    for (int ks = 0; ks < 32; ks++) {
        cp_wait<2>();
        __syncthreads();
        int sn = ks + 3;
        if (sn < 32) issue(sn, sn & 3);
        cp_commit();
        const float* Ab = sm + (ks & 3) * STG;
        const float* Bb = Ab + 2560;
#pragma unroll
        for (int kk = 0; kk < 2; kk++) {
            wmma::fragment<wmma::matrix_a, 16, 16, 8, wmma::precision::tf32, wmma::row_major> a[2];
            wmma::fragment<wmma::matrix_b, 16, 16, 8, wmma::precision::tf32, wmma::row_major> b[4];
            wmma::load_matrix_sync(a[0], Ab + (wm * 32) * A_LD + kk * 8, A_LD);
            wmma::load_matrix_sync(a[1], Ab + (wm * 32 + 16) * A_LD + kk * 8, A_LD);
#pragma unroll
            for (int ni = 0; ni < 4; ni++)
                wmma::load_matrix_sync(b[ni], Bb + (kk * 8) * B_LD + wn * 64 + ni * 16, B_LD);
#pragma unroll
            for (int mi = 0; mi < 2; mi++)
#pragma unroll
                for (int ni = 0; ni < 4; ni++)
                    wmma::mma_sync(acc[mi][ni], a[mi], b[ni], acc[mi][ni]);
        }
    }

    // epilogue: smem roundtrip -> bias + gelu + gate-scale + tf32 cvt
    __syncthreads();
    float* Cs = sm;   // [128][136]
#pragma unroll
    for (int mi = 0; mi < 2; mi++)
#pragma unroll
        for (int ni = 0; ni < 4; ni++)
            wmma::store_matrix_sync(Cs + (size_t)(wm * 32 + mi * 16) * B_LD + wn * 64 + ni * 16,
                                    acc[mi][ni], B_LD, wmma::mem_row_major);
    __syncthreads();
    float* hb = g_hbuf + (size_t)(e * CAPMAX + row0) * HH + h0;
#pragma unroll
    for (int i = 0; i < 64; i++) {
        int idx = tid + i * 256;
        int r = idx >> 7, c = idx & 127;
        float v = Cs[r * B_LD + c] + b1s[c];
        v = 0.5f * v * (1.f + erff(v * 0.7071067811865476f));
        hb[(size_t)r * HH + c] = to_tf32(v * swt[r]);
    }
}

// ---------------- kernel 4: GEMM2  ybuf = hbuf_scaled @ W2[e] + wt*b2 ----------------
__global__ void __launch_bounds__(256, 2) gemm2_kernel(const float* __restrict__ b2) {
    extern __shared__ float sm[];
    unsigned int smb = (unsigned int)__cvta_generic_to_shared(sm);

    int e = blockIdx.z;
    int rows = g_cnt[e];
    int row0 = blockIdx.x * 128;
    if (row0 >= rows) return;
    int d0 = blockIdx.y * 128;

    int tid = threadIdx.x;
    const float* hbase = g_hbuf + (size_t)(e * CAPMAX + row0) * HH;
    const float* w2e = g_w2t + (size_t)e * HH * DD;

    auto issue = [&](int s, int b) {
        int k0 = s * 16;
        unsigned int Ad = smb + (unsigned int)(b * STG) * 4u;
        unsigned int Bd = Ad + 2560u * 4u;
#pragma unroll
        for (int it = 0; it < 2; it++) {
            int idx = tid + it * 256;
            int r = idx >> 2, c = idx & 3;
            int ok = (row0 + r < rows) ? 16 : 0;
            cp16(Ad + (unsigned int)(r * A_LD + c * 4) * 4u,
                 hbase + (size_t)r * HH + k0 + c * 4, ok);
        }
#pragma unroll
        for (int it = 0; it < 2; it++) {
            int idx = tid + it * 256;
            int kr = idx >> 5, c = idx & 31;
            cp16(Bd + (unsigned int)(kr * B_LD + c * 4) * 4u,
                 w2e + (size_t)(k0 + kr) * DD + d0 + c * 4, 16);
        }
    };

    issue(0, 0); cp_commit();
    issue(1, 1); cp_commit();
    issue(2, 2); cp_commit();

    int wid = tid >> 5, wm = wid & 3, wn = wid >> 2;
    wmma::fragment<wmma::accumulator, 16, 16, 8, float> acc[2][4];
#pragma unroll
    for (int mi = 0; mi < 2; mi++)
#pragma unroll
        for (int ni = 0; ni < 4; ni++) wmma::fill_fragment(acc[mi][ni], 0.f);

    for (int ks = 0; ks < 128; ks++) {
        cp_wait<2>();
        __syncthreads();
        int sn = ks + 3;
        if (sn < 128) issue(sn, sn & 3);
        cp_commit();
        const float* Ab = sm + (ks & 3) * STG;
        const float* Bb = Ab + 2560;
#pragma unroll
        for (int kk = 0; kk < 2; kk++) {
            wmma::fragment<wmma::matrix_a, 16, 16, 8, wmma::precision::tf32, wmma::row_major> a[2];
            wmma::fragment<wmma::matrix_b, 16, 16, 8, wmma::precision::tf32, wmma::row_major> b[4];
            wmma::load_matrix_sync(a[0], Ab + (wm * 32) * A_LD + kk * 8, A_LD);
            wmma::load_matrix_sync(a[1], Ab + (wm * 32 + 16) * A_LD + kk * 8, A_LD);
#pragma unroll
            for (int ni = 0; ni < 4; ni++)
                wmma::load_matrix_sync(b[ni], Bb + (kk * 8) * B_LD + wn * 64 + ni * 16, B_LD);
#pragma unroll
            for (int mi = 0; mi < 2; mi++)
#pragma unroll
                for (int ni = 0; ni < 4; ni++)
                    wmma::mma_sync(acc[mi][ni], a[mi], b[ni], acc[mi][ni]);
        }
    }

    // rank-1 bias slab: A[:,0] = wt, B[0,:] = b2 segment (both tf32)
    __syncthreads();
    float* Ab0 = sm;
    float* Bb0 = sm + 2560;
    for (int i = tid; i < 2560; i += 256) Ab0[i] = 0.f;
    for (int i = tid; i < 8 * B_LD; i += 256) Bb0[i] = 0.f;
    __syncthreads();
    if (tid < 128) {
        int r = row0 + tid;
        Ab0[tid * A_LD] = to_tf32((r < rows) ? g_dwt[e * CAPMAX + r] : 0.f);
        Bb0[tid] = to_tf32(b2[e * DD + d0 + tid]);
    }
    __syncthreads();
    {
        wmma::fragment<wmma::matrix_a, 16, 16, 8, wmma::precision::tf32, wmma::row_major> a[2];
        wmma::fragment<wmma::matrix_b, 16, 16, 8, wmma::precision::tf32, wmma::row_major> b[4];
        wmma::load_matrix_sync(a[0], Ab0 + (wm * 32) * A_LD, A_LD);
        wmma::load_matrix_sync(a[1], Ab0 + (wm * 32 + 16) * A_LD, A_LD);
#pragma unroll
        for (int ni = 0; ni < 4; ni++)
            wmma::load_matrix_sync(b[ni], Bb0 + wn * 64 + ni * 16, B_LD);
#pragma unroll
        for (int mi = 0; mi < 2; mi++)
#pragma unroll
            for (int ni = 0; ni < 4; ni++)
                wmma::mma_sync(acc[mi][ni], a[mi], b[ni], acc[mi][ni]);
    }

    float* yb = g_ybuf + (size_t)(e * CAPMAX + row0 + wm * 32) * DD + d0 + wn * 64;
#pragma unroll
    for (int mi = 0; mi < 2; mi++)
#pragma unroll
        for (int ni = 0; ni < 4; ni++)
            wmma::store_matrix_sync(yb + (size_t)mi * 16 * DD + ni * 16, acc[mi][ni], DD,
                                    wmma::mem_row_major);
}

// ---------------- kernel 5: gather-combine ----------------
__global__ void __launch_bounds__(256) combine_kernel(float* __restrict__ out) {
    int i = blockIdx.x * 256 + threadIdx.x;
    int t = i >> 7;                    // DD/4 = 128 float4 per token
    int d = i & 127;
    int i0 = g_inv[t], i1 = g_inv[TT + t];
    float4 a = make_float4(0.f, 0.f, 0.f, 0.f), b = a;
    if (i0 >= 0) a = *((const float4*)g_ybuf + (size_t)i0 * 128 + d);
    if (i1 >= 0) b = *((const float4*)g_ybuf + (size_t)i1 * 128 + d);
    ((float4*)out)[i] = make_float4(a.x + b.x, a.y + b.y, a.z + b.z, a.w + b.w);
}

// ---------------- launch ----------------
extern "C" void kernel_launch(void* const* d_in, const int* in_sizes, int n_in,
                              void* d_out, int out_size) {
    const float* x  = (const float*)d_in[0];
    const float* gw = (const float*)d_in[1];
    const float* w1 = (const float*)d_in[2];
    const float* b1 = (const float*)d_in[3];
    const float* w2 = (const float*)d_in[4];
    const float* b2 = (const float*)d_in[5];
    float* out = (float*)d_out;

    cudaFuncSetAttribute(gemm1_kernel, cudaFuncAttributeMaxDynamicSharedMemorySize, G1_SMEM);
    cudaFuncSetAttribute(gemm2_kernel, cudaFuncAttributeMaxDynamicSharedMemorySize, G2_SMEM);

    zero_imp_kernel<<<1, 32>>>();
    router_kernel<<<TT / 8, 256>>>(x, gw);
    scan_kernel<<<1, 1024>>>(out, out_size);
    cvt_x_kernel<<<(TT * DD / 4) / 256, 256>>>((const float4*)x);
    cvt_w1_kernel<<<(EE * DD * HH / 4) / 256, 256>>>((const float4*)w1);
    cvt_w2_kernel<<<(EE * HH * DD / 4) / 256, 256>>>((const float4*)w2);
    gemm1_kernel<<<dim3(CAPMAX / 128, HH / 128, EE), 256, G1_SMEM>>>(b1);
    gemm2_kernel<<<dim3(CAPMAX / 128, DD / 128, EE), 256, G2_SMEM>>>(b2);
    combine_kernel<<<(TT * DD / 4) / 256, 256>>>(out);
}

// round 9
// speedup vs baseline: 1.2328x; 1.0192x over previous
#include <cuda_runtime.h>
#include <cstdint>
#include <mma.h>
#include <math.h>

using namespace nvcuda;

#define TT 4096
#define DD 512
#define HH 2048
#define EE 8
#define CAP 1075          // round(2*4096*1.05/8)
#define CAPMAX 1152       // 9 * 128

// ---------------- static device scratch ----------------
__device__ float g_imp[EE];
__device__ int   g_ti[2 * TT];
__device__ float g_tg[2 * TT];
__device__ int   g_cnt[EE];
__device__ int   g_dtok[EE * CAPMAX];
__device__ float g_dwt[EE * CAPMAX];
__device__ int   g_inv[2 * TT];
__device__ __align__(16) float g_xt [(size_t)TT * DD];            // tf32-rounded x
__device__ __align__(16) float g_hbuf[(size_t)EE * CAPMAX * HH];  // tf32 wt*gelu(h)
__device__ __align__(16) float g_ybuf[(size_t)EE * CAPMAX * DD];

__device__ __forceinline__ float to_tf32(float x) {
    float r; asm("cvt.rna.tf32.f32 %0, %1;" : "=f"(r) : "f"(x)); return r;
}
__device__ __forceinline__ float gelu_f(float v) {
    return 0.5f * v * (1.f + erff(v * 0.7071067811865476f));
}
__device__ __forceinline__ void cp16(unsigned int dst, const float* src, int sz) {
    asm volatile("cp.async.cg.shared.global [%0], [%1], 16, %2;"
                 :: "r"(dst), "l"(src), "r"(sz));
}
__device__ __forceinline__ void cp_commit() { asm volatile("cp.async.commit_group;"); }
template<int N> __device__ __forceinline__ void cp_wait() {
    asm volatile("cp.async.wait_group %0;" :: "n"(N));
}

// ---------------- tf32 pre-convert of x ----------------
__global__ void cvt_x_kernel(const float4* __restrict__ s) {
    int i = blockIdx.x * 256 + threadIdx.x;
    float4 v = s[i];
    ((float4*)g_xt)[i] = make_float4(to_tf32(v.x), to_tf32(v.y), to_tf32(v.z), to_tf32(v.w));
}

// ---------------- kernel 0 ----------------
__global__ void zero_imp_kernel() {
    if (threadIdx.x < EE) g_imp[threadIdx.x] = 0.f;
}

// ---------------- kernel 1: router ----------------
__global__ void __launch_bounds__(256) router_kernel(const float* __restrict__ x,
                                                     const float* __restrict__ gw) {
    __shared__ float sgw[EE * DD];
    int tid = threadIdx.x;
    for (int i = tid; i < EE * DD / 4; i += 256)
        ((float4*)sgw)[i] = ((const float4*)gw)[i];
    __syncthreads();

    int wid = tid >> 5, lane = tid & 31;
    int t = blockIdx.x * 8 + wid;
    const float* xr = x + (size_t)t * DD;

    float acc[EE];
#pragma unroll
    for (int e = 0; e < EE; e++) acc[e] = 0.f;
#pragma unroll
    for (int i = 0; i < DD / 32; i++) {
        int d = lane + i * 32;
        float xv = xr[d];
#pragma unroll
        for (int e = 0; e < EE; e++) acc[e] = fmaf(xv, sgw[e * DD + d], acc[e]);
    }
#pragma unroll
    for (int e = 0; e < EE; e++) {
#pragma unroll
        for (int o = 16; o > 0; o >>= 1)
            acc[e] += __shfl_xor_sync(0xffffffffu, acc[e], o);
    }
    if (lane == 0) {
        float mx = acc[0];
#pragma unroll
        for (int e = 1; e < EE; e++) mx = fmaxf(mx, acc[e]);
        float g[EE], s = 0.f;
#pragma unroll
        for (int e = 0; e < EE; e++) { g[e] = expf(acc[e] - mx); s += g[e]; }
        float inv = 1.f / s;
#pragma unroll
        for (int e = 0; e < EE; e++) { g[e] *= inv; atomicAdd(&g_imp[e], g[e]); }
        int i0 = 0; float g0 = g[0];
#pragma unroll
        for (int e = 1; e < EE; e++) if (g[e] > g0) { g0 = g[e]; i0 = e; }
        int i1 = -1; float g1 = -1.f;
#pragma unroll
        for (int e = 0; e < EE; e++) if (e != i0 && g[e] > g1) { g1 = g[e]; i1 = e; }
        g_ti[t] = i0;        g_ti[TT + t] = i1;
        g_tg[t] = g0;        g_tg[TT + t] = g1;
    }
}

// ---------------- kernel 2: slot-major capacity scan + losses ----------------
__global__ void __launch_bounds__(1024) scan_kernel(float* __restrict__ out, int out_size) {
    int i = threadIdx.x;
    int myexp[8];
    unsigned long long c0 = 0, c1 = 0;
#pragma unroll
    for (int u = 0; u < 8; u++) {
        int j = i * 8 + u;
        int e = g_ti[j];
        myexp[u] = e;
        if (e < 4) c0 += 1ULL << (16 * e); else c1 += 1ULL << (16 * (e - 4));
    }
    __shared__ unsigned long long sA[1024], sB[1024];
    sA[i] = c0; sB[i] = c1;
    __syncthreads();
    for (int off = 1; off < 1024; off <<= 1) {
        unsigned long long a = 0, b = 0;
        if (i >= off) { a = sA[i - off]; b = sB[i - off]; }
        __syncthreads();
        sA[i] += a; sB[i] += b;
        __syncthreads();
    }
    unsigned long long e0 = sA[i] - c0, e1 = sB[i] - c1;
    int run[8];
#pragma unroll
    for (int e = 0; e < 4; e++) {
        run[e]     = (int)((e0 >> (16 * e)) & 0xFFFF);
        run[e + 4] = (int)((e1 >> (16 * e)) & 0xFFFF);
    }
#pragma unroll
    for (int u = 0; u < 8; u++) {
        int j = i * 8 + u;
        int e = myexp[u];
        int pos = run[e]++;
        if (pos < CAP) {
            int o = e * CAPMAX + pos;
            g_dtok[o] = j & (TT - 1);
            g_dwt[o]  = g_tg[j];
            g_inv[j]  = o;
        } else {
            g_inv[j] = -1;
        }
    }
    if (i == 1023) {
        unsigned long long t0 = sA[1023], t1 = sB[1023];
        float tpe[8];
        for (int e = 0; e < 4; e++) {
            int a = min((int)((t0 >> (16 * e)) & 0xFFFF), CAP);
            int b = min((int)((t1 >> (16 * e)) & 0xFFFF), CAP);
            g_cnt[e] = a;     tpe[e] = (float)a;
            g_cnt[e + 4] = b; tpe[e + 4] = (float)b;
        }
        double s = 0, ss = 0;
        for (int e = 0; e < 8; e++) { s += tpe[e]; ss += (double)tpe[e] * tpe[e]; }
        double m = s / 8.0, var = ss / 8.0 - m * m; if (var < 0) var = 0;
        double l_load = var / ((m + 1e-6) * (m + 1e-6));
        double s2 = 0, sq2 = 0;
        for (int e = 0; e < 8; e++) { double v = g_imp[e]; s2 += v; sq2 += v * v; }
        double m2 = s2 / 8.0, v2 = sq2 / 8.0 - m2 * m2; if (v2 < 0) v2 = 0;
        double imp_loss = v2 / ((m2 + 1e-6) * (m2 + 1e-6));
        if (out_size >= TT * DD + 2) {
            out[TT * DD]     = (float)(0.5 * (imp_loss + l_load));
            out[TT * DD + 1] = (float)l_load;
        }
    }
}

// ============ GEMM tiling ============
// Block tile 128x128, k-slab 32, 3-stage cp.async.
// Stage floats: A [128][36] = 4608, B [32][132] = 4224 -> 8832.
#define A_LD 36
#define B_LD 132
#define STG  8832
#define OFF_CTRL (3 * STG)          // toks[128] | swt[128] | bias[128]
#define GSMEM_BYTES ((3 * STG + 384) * 4)

// ---------------- kernel 3: GEMM1  hbuf = wt * gelu(Xg @ W1[e] + b1[e]) (tf32 out) ----------------
__global__ void __launch_bounds__(256, 2) gemm1_kernel(const float* __restrict__ w1,
                                                       const float* __restrict__ b1) {
    extern __shared__ float sm[];
    unsigned int smb = (unsigned int)__cvta_generic_to_shared(sm);
    int*   toks = (int*)(sm + OFF_CTRL);
    float* swt  = sm + OFF_CTRL + 128;
    float* bis  = sm + OFF_CTRL + 256;

    int e = blockIdx.z;
    int rows = g_cnt[e];
    int row0 = blockIdx.x * 128;
    if (row0 >= rows) return;
    int h0 = blockIdx.y * 128;

    int tid = threadIdx.x;
    if (tid < 128) {
        int r = row0 + tid;
        toks[tid] = (r < rows) ? g_dtok[e * CAPMAX + r] : -1;
        swt[tid]  = (r < rows) ? g_dwt[e * CAPMAX + r] : 0.f;
        bis[tid]  = b1[e * HH + h0 + tid];
    }
    __syncthreads();

    const float* w1e = w1 + (size_t)e * DD * HH;   // raw fp32 [D][H]

    auto fill = [&](int s) {
        int k0 = s * 32;
        unsigned int Ad = smb + (unsigned int)((s % 3) * STG) * 4u;
        unsigned int Bd = Ad + 4608u * 4u;
#pragma unroll
        for (int it = 0; it < 4; it++) {           // A: 128 rows x 8 float4
            int idx = tid + it * 256;
            int r = idx >> 3, c = idx & 7;
            int tok = toks[r];
            cp16(Ad + (unsigned int)(r * A_LD + c * 4) * 4u,
                 g_xt + (size_t)(tok < 0 ? 0 : tok) * DD + k0 + c * 4, tok < 0 ? 0 : 16);
        }
#pragma unroll
        for (int it = 0; it < 4; it++) {           // B: 32 rows x 32 float4
            int idx = tid + it * 256;
            int kr = idx >> 5, c = idx & 31;
            cp16(Bd + (unsigned int)(kr * B_LD + c * 4) * 4u,
                 w1e + (size_t)(k0 + kr) * HH + h0 + c * 4, 16);
        }
    };

    fill(0); cp_commit();
    fill(1); cp_commit();

    int wid = tid >> 5, wm = wid & 3, wn = wid >> 2;   // warp tile 32(M) x 64(N)
    wmma::fragment<wmma::accumulator, 16, 16, 8, float> acc[2][4];
#pragma unroll
    for (int mi = 0; mi < 2; mi++)
#pragma unroll
        for (int ni = 0; ni < 4; ni++) wmma::fill_fragment(acc[mi][ni], 0.f);

    const int KS = DD / 32;   // 16
    for (int ks = 0; ks < KS; ks++) {
        cp_wait<1>();
        __syncthreads();
        if (ks + 2 < KS) fill(ks + 2);
        cp_commit();
        const float* Ab = sm + (ks % 3) * STG;
        const float* Bb = Ab + 4608;
#pragma unroll
        for (int kk = 0; kk < 4; kk++) {
            wmma::fragment<wmma::matrix_a, 16, 16, 8, wmma::precision::tf32, wmma::row_major> a[2];
            wmma::fragment<wmma::matrix_b, 16, 16, 8, wmma::precision::tf32, wmma::row_major> b[4];
            wmma::load_matrix_sync(a[0], Ab + (wm * 32) * A_LD + kk * 8, A_LD);
            wmma::load_matrix_sync(a[1], Ab + (wm * 32 + 16) * A_LD + kk * 8, A_LD);
#pragma unroll
            for (int ni = 0; ni < 4; ni++)
                wmma::load_matrix_sync(b[ni], Bb + (kk * 8) * B_LD + wn * 64 + ni * 16, B_LD);
#pragma unroll
            for (int mi = 0; mi < 2; mi++)
#pragma unroll
                for (int ni = 0; ni < 4; ni++)
                    wmma::mma_sync(acc[mi][ni], a[mi], b[ni], acc[mi][ni]);
        }
    }

    // epilogue: smem roundtrip -> bias + gelu + gate-scale + tf32 cvt
    __syncthreads();
    float* Cs = sm;   // [128][B_LD]
#pragma unroll
    for (int mi = 0; mi < 2; mi++)
#pragma unroll
        for (int ni = 0; ni < 4; ni++)
            wmma::store_matrix_sync(Cs + (size_t)(wm * 32 + mi * 16) * B_LD + wn * 64 + ni * 16,
                                    acc[mi][ni], B_LD, wmma::mem_row_major);
    __syncthreads();
    float* hb = g_hbuf + (size_t)(e * CAPMAX + row0) * HH + h0;
#pragma unroll
    for (int i = 0; i < 64; i++) {
        int idx = tid + i * 256;
        int r = idx >> 7, c = idx & 127;
        float v = Cs[r * B_LD + c] + bis[c];
        v = gelu_f(v);
        hb[(size_t)r * HH + c] = to_tf32(v * swt[r]);
    }
}

// ---------------- kernel 4: GEMM2  ybuf = hbuf_scaled @ W2[e] + wt*b2 ----------------
__global__ void __launch_bounds__(256, 2) gemm2_kernel(const float* __restrict__ w2,
                                                       const float* __restrict__ b2) {
    extern __shared__ float sm[];
    unsigned int smb = (unsigned int)__cvta_generic_to_shared(sm);
    float* swt = sm + OFF_CTRL + 128;
    float* bis = sm + OFF_CTRL + 256;

    int e = blockIdx.z;
    int rows = g_cnt[e];
    int row0 = blockIdx.x * 128;
    if (row0 >= rows) return;
    int d0 = blockIdx.y * 128;

    int tid = threadIdx.x;
    if (tid < 128) {
        int r = row0 + tid;
        swt[tid] = (r < rows) ? g_dwt[e * CAPMAX + r] : 0.f;
        bis[tid] = b2[e * DD + d0 + tid];
    }
    __syncthreads();

    const float* hbase = g_hbuf + (size_t)(e * CAPMAX + row0) * HH;
    const float* w2e = w2 + (size_t)e * HH * DD;   // raw fp32 [H][D]

    auto fill = [&](int s) {
        int k0 = s * 32;
        unsigned int Ad = smb + (unsigned int)((s % 3) * STG) * 4u;
        unsigned int Bd = Ad + 4608u * 4u;
#pragma unroll
        for (int it = 0; it < 4; it++) {
            int idx = tid + it * 256;
            int r = idx >> 3, c = idx & 7;
            cp16(Ad + (unsigned int)(r * A_LD + c * 4) * 4u,
                 hbase + (size_t)r * HH + k0 + c * 4, 16);
        }
#pragma unroll
        for (int it = 0; it < 4; it++) {
            int idx = tid + it * 256;
            int kr = idx >> 5, c = idx & 31;
            cp16(Bd + (unsigned int)(kr * B_LD + c * 4) * 4u,
                 w2e + (size_t)(k0 + kr) * DD + d0 + c * 4, 16);
        }
    };

    fill(0); cp_commit();
    fill(1); cp_commit();

    int wid = tid >> 5, wm = wid & 3, wn = wid >> 2;
    wmma::fragment<wmma::accumulator, 16, 16, 8, float> acc[2][4];
#pragma unroll
    for (int mi = 0; mi < 2; mi++)
#pragma unroll
        for (int ni = 0; ni < 4; ni++) wmma::fill_fragment(acc[mi][ni], 0.f);

    const int KS = HH / 32;   // 64
    for (int ks = 0; ks < KS; ks++) {
        cp_wait<1>();
        __syncthreads();
        if (ks + 2 < KS) fill(ks + 2);
        cp_commit();
        const float* Ab = sm + (ks % 3) * STG;
        const float* Bb = Ab + 4608;
#pragma unroll
        for (int kk = 0; kk < 4; kk++) {
            wmma::fragment<wmma::matrix_a, 16, 16, 8, wmma::precision::tf32, wmma::row_major> a[2];
            wmma::fragment<wmma::matrix_b, 16, 16, 8, wmma::precision::tf32, wmma::row_major> b[4];
            wmma::load_matrix_sync(a[0], Ab + (wm * 32) * A_LD + kk * 8, A_LD);
            wmma::load_matrix_sync(a[1], Ab + (wm * 32 + 16) * A_LD + kk * 8, A_LD);
#pragma unroll
            for (int ni = 0; ni < 4; ni++)
                wmma::load_matrix_sync(b[ni], Bb + (kk * 8) * B_LD + wn * 64 + ni * 16, B_LD);
#pragma unroll
            for (int mi = 0; mi < 2; mi++)
#pragma unroll
                for (int ni = 0; ni < 4; ni++)
                    wmma::mma_sync(acc[mi][ni], a[mi], b[ni], acc[mi][ni]);
        }
    }

    // epilogue: smem roundtrip -> + wt*b2, store to ybuf
    __syncthreads();
    float* Cs = sm;
#pragma unroll
    for (int mi = 0; mi < 2; mi++)
#pragma unroll
        for (int ni = 0; ni < 4; ni++)
            wmma::store_matrix_sync(Cs + (size_t)(wm * 32 + mi * 16) * B_LD + wn * 64 + ni * 16,
                                    acc[mi][ni], B_LD, wmma::mem_row_major);
    __syncthreads();
    float* yb = g_ybuf + (size_t)(e * CAPMAX + row0) * DD + d0;
#pragma unroll
    for (int i = 0; i < 64; i++) {
        int idx = tid + i * 256;
        int r = idx >> 7, c = idx & 127;
        yb[(size_t)r * DD + c] = Cs[r * B_LD + c] + swt[r] * bis[c];
    }
}

// ---------------- kernel 5: gather-combine ----------------
__global__ void __launch_bounds__(256) combine_kernel(float* __restrict__ out) {
    int i = blockIdx.x * 256 + threadIdx.x;
    int t = i >> 7;                    // DD/4 = 128 float4 per token
    int d = i & 127;
    int i0 = g_inv[t], i1 = g_inv[TT + t];
    float4 a = make_float4(0.f, 0.f, 0.f, 0.f), b = a;
    if (i0 >= 0) a = *((const float4*)g_ybuf + (size_t)i0 * 128 + d);
    if (i1 >= 0) b = *((const float4*)g_ybuf + (size_t)i1 * 128 + d);
    ((float4*)out)[i] = make_float4(a.x + b.x, a.y + b.y, a.z + b.z, a.w + b.w);
}

// ---------------- launch ----------------
extern "C" void kernel_launch(void* const* d_in, const int* in_sizes, int n_in,
                              void* d_out, int out_size) {
    const float* x  = (const float*)d_in[0];
    const float* gw = (const float*)d_in[1];
    const float* w1 = (const float*)d_in[2];
    const float* b1 = (const float*)d_in[3];
    const float* w2 = (const float*)d_in[4];
    const float* b2 = (const float*)d_in[5];
    float* out = (float*)d_out;

    cudaFuncSetAttribute(gemm1_kernel, cudaFuncAttributeMaxDynamicSharedMemorySize, GSMEM_BYTES);
    cudaFuncSetAttribute(gemm2_kernel, cudaFuncAttributeMaxDynamicSharedMemorySize, GSMEM_BYTES);

    zero_imp_kernel<<<1, 32>>>();
    router_kernel<<<TT / 8, 256>>>(x, gw);
    scan_kernel<<<1, 1024>>>(out, out_size);
    cvt_x_kernel<<<(TT * DD / 4) / 256, 256>>>((const float4*)x);
    gemm1_kernel<<<dim3(CAPMAX / 128, HH / 128, EE), 256, GSMEM_BYTES>>>(w1, b1);
    gemm2_kernel<<<dim3(CAPMAX / 128, DD / 128, EE), 256, GSMEM_BYTES>>>(w2, b2);
    combine_kernel<<<(TT * DD / 4) / 256, 256>>>(out);
}

// round 10
// speedup vs baseline: 3.2002x; 2.5960x over previous
#include <cuda_runtime.h>
#include <cuda_fp16.h>
#include <cstdint>
#include <mma.h>
#include <math.h>

using namespace nvcuda;

#define TT 4096
#define DD 512
#define HH 2048
#define EE 8
#define CAP 1075          // round(2*4096*1.05/8)
#define CAPMAX 1152       // 9 * 128

// ---------------- static device scratch ----------------
__device__ float g_imp[EE];
__device__ int   g_ti[2 * TT];
__device__ float g_tg[2 * TT];
__device__ int   g_cnt[EE];
__device__ int   g_dtok[EE * CAPMAX];
__device__ float g_dwt[EE * CAPMAX];
__device__ int   g_inv[2 * TT];
__device__ __align__(16) __half g_xh [(size_t)TT * DD];             // fp16 x       [T][D]
__device__ __align__(16) __half g_w1h[(size_t)EE * DD * HH];        // fp16 W1      [E][D][H]
__device__ __align__(16) __half g_w2h[(size_t)EE * HH * DD];        // fp16 W2      [E][H][D]
__device__ __align__(16) __half g_hbuf[(size_t)EE * CAPMAX * HH];   // fp16 wt*gelu(h)
__device__ __align__(16) float  g_ybuf[(size_t)EE * CAPMAX * DD];

__device__ __forceinline__ float gelu_f(float v) {
    return 0.5f * v * (1.f + erff(v * 0.7071067811865476f));
}
__device__ __forceinline__ void cp16(unsigned int dst, const void* src, int sz) {
    asm volatile("cp.async.cg.shared.global [%0], [%1], 16, %2;"
                 :: "r"(dst), "l"(src), "r"(sz));
}
__device__ __forceinline__ void cp_commit() { asm volatile("cp.async.commit_group;"); }
template<int N> __device__ __forceinline__ void cp_wait() {
    asm volatile("cp.async.wait_group %0;" :: "n"(N));
}
__device__ __forceinline__ uint4 pack8h(float4 v0, float4 v1) {
    __half2 p0 = __floats2half2_rn(v0.x, v0.y);
    __half2 p1 = __floats2half2_rn(v0.z, v0.w);
    __half2 p2 = __floats2half2_rn(v1.x, v1.y);
    __half2 p3 = __floats2half2_rn(v1.z, v1.w);
    uint4 o;
    o.x = *reinterpret_cast<unsigned*>(&p0);
    o.y = *reinterpret_cast<unsigned*>(&p1);
    o.z = *reinterpret_cast<unsigned*>(&p2);
    o.w = *reinterpret_cast<unsigned*>(&p3);
    return o;
}

// ---------------- fp16 pre-convert kernels (RN, unbiased) ----------------
__global__ void cvtx_kernel(const float4* __restrict__ s) {
    int i = blockIdx.x * 256 + threadIdx.x;
    ((uint4*)g_xh)[i] = pack8h(s[2 * i], s[2 * i + 1]);
}
__global__ void cvtw1_kernel(const float4* __restrict__ s) {
    int i = blockIdx.x * 256 + threadIdx.x;
    ((uint4*)g_w1h)[i] = pack8h(s[2 * i], s[2 * i + 1]);
}
__global__ void cvtw2_kernel(const float4* __restrict__ s) {
    int i = blockIdx.x * 256 + threadIdx.x;
    ((uint4*)g_w2h)[i] = pack8h(s[2 * i], s[2 * i + 1]);
}

// ---------------- kernel 0 ----------------
__global__ void zero_imp_kernel() {
    if (threadIdx.x < EE) g_imp[threadIdx.x] = 0.f;
}

// ---------------- kernel 1: router ----------------
__global__ void __launch_bounds__(256) router_kernel(const float* __restrict__ x,
                                                     const float* __restrict__ gw) {
    __shared__ float sgw[EE * DD];
    int tid = threadIdx.x;
    for (int i = tid; i < EE * DD / 4; i += 256)
        ((float4*)sgw)[i] = ((const float4*)gw)[i];
    __syncthreads();

    int wid = tid >> 5, lane = tid & 31;
    int t = blockIdx.x * 8 + wid;
    const float* xr = x + (size_t)t * DD;

    float acc[EE];
#pragma unroll
    for (int e = 0; e < EE; e++) acc[e] = 0.f;
#pragma unroll
    for (int i = 0; i < DD / 32; i++) {
        int d = lane + i * 32;
        float xv = xr[d];
#pragma unroll
        for (int e = 0; e < EE; e++) acc[e] = fmaf(xv, sgw[e * DD + d], acc[e]);
    }
#pragma unroll
    for (int e = 0; e < EE; e++) {
#pragma unroll
        for (int o = 16; o > 0; o >>= 1)
            acc[e] += __shfl_xor_sync(0xffffffffu, acc[e], o);
    }
    if (lane == 0) {
        float mx = acc[0];
#pragma unroll
        for (int e = 1; e < EE; e++) mx = fmaxf(mx, acc[e]);
        float g[EE], s = 0.f;
#pragma unroll
        for (int e = 0; e < EE; e++) { g[e] = expf(acc[e] - mx); s += g[e]; }
        float inv = 1.f / s;
#pragma unroll
        for (int e = 0; e < EE; e++) { g[e] *= inv; atomicAdd(&g_imp[e], g[e]); }
        int i0 = 0; float g0 = g[0];
#pragma unroll
        for (int e = 1; e < EE; e++) if (g[e] > g0) { g0 = g[e]; i0 = e; }
        int i1 = -1; float g1 = -1.f;
#pragma unroll
        for (int e = 0; e < EE; e++) if (e != i0 && g[e] > g1) { g1 = g[e]; i1 = e; }
        g_ti[t] = i0;        g_ti[TT + t] = i1;
        g_tg[t] = g0;        g_tg[TT + t] = g1;
    }
}

// ---------------- kernel 2: slot-major capacity scan + losses ----------------
__global__ void __launch_bounds__(1024) scan_kernel(float* __restrict__ out, int out_size) {
    int i = threadIdx.x;
    int myexp[8];
    unsigned long long c0 = 0, c1 = 0;
#pragma unroll
    for (int u = 0; u < 8; u++) {
        int j = i * 8 + u;
        int e = g_ti[j];
        myexp[u] = e;
        if (e < 4) c0 += 1ULL << (16 * e); else c1 += 1ULL << (16 * (e - 4));
    }
    __shared__ unsigned long long sA[1024], sB[1024];
    sA[i] = c0; sB[i] = c1;
    __syncthreads();
    for (int off = 1; off < 1024; off <<= 1) {
        unsigned long long a = 0, b = 0;
        if (i >= off) { a = sA[i - off]; b = sB[i - off]; }
        __syncthreads();
        sA[i] += a; sB[i] += b;
        __syncthreads();
    }
    unsigned long long e0 = sA[i] - c0, e1 = sB[i] - c1;
    int run[8];
#pragma unroll
    for (int e = 0; e < 4; e++) {
        run[e]     = (int)((e0 >> (16 * e)) & 0xFFFF);
        run[e + 4] = (int)((e1 >> (16 * e)) & 0xFFFF);
    }
#pragma unroll
    for (int u = 0; u < 8; u++) {
        int j = i * 8 + u;
        int e = myexp[u];
        int pos = run[e]++;
        if (pos < CAP) {
            int o = e * CAPMAX + pos;
            g_dtok[o] = j & (TT - 1);
            g_dwt[o]  = g_tg[j];
            g_inv[j]  = o;
        } else {
            g_inv[j] = -1;
        }
    }
    if (i == 1023) {
        unsigned long long t0 = sA[1023], t1 = sB[1023];
        float tpe[8];
        for (int e = 0; e < 4; e++) {
            int a = min((int)((t0 >> (16 * e)) & 0xFFFF), CAP);
            int b = min((int)((t1 >> (16 * e)) & 0xFFFF), CAP);
            g_cnt[e] = a;     tpe[e] = (float)a;
            g_cnt[e + 4] = b; tpe[e + 4] = (float)b;
        }
        double s = 0, ss = 0;
        for (int e = 0; e < 8; e++) { s += tpe[e]; ss += (double)tpe[e] * tpe[e]; }
        double m = s / 8.0, var = ss / 8.0 - m * m; if (var < 0) var = 0;
        double l_load = var / ((m + 1e-6) * (m + 1e-6));
        double s2 = 0, sq2 = 0;
        for (int e = 0; e < 8; e++) { double v = g_imp[e]; s2 += v; sq2 += v * v; }
        double m2 = s2 / 8.0, v2 = sq2 / 8.0 - m2 * m2; if (v2 < 0) v2 = 0;
        double imp_loss = v2 / ((m2 + 1e-6) * (m2 + 1e-6));
        if (out_size >= TT * DD + 2) {
            out[TT * DD]     = (float)(0.5 * (imp_loss + l_load));
            out[TT * DD + 1] = (float)l_load;
        }
    }
}

// ============ fp16 GEMM tiling ============
// Block tile 128x128, k-slab 64, 3-stage cp.async, warp tile 32x64, wmma m16n16k16 fp16->f32.
// Stage: A 128x72 halves (18432 B) + B 64x136 halves (17408 B) = 35840 B; x3 = 107520 B.
// Epilogue C tile (fp32 128x136 = 69632 B) reuses stage area.
#define A_LDH 72
#define B_LDH 136
#define STG_H 17920                  // halves per stage
#define STG_B 35840                  // bytes per stage
#define OFF_CTRL 26880               // floats (= 107520 B)
#define GSMEM_BYTES ((OFF_CTRL + 384) * 4)

// ---------------- kernel 3: GEMM1  hbuf(fp16) = wt * gelu(Xg @ W1[e] + b1[e]) ----------------
__global__ void __launch_bounds__(256, 2) gemm1_kernel(const float* __restrict__ b1) {
    extern __shared__ float sm[];
    unsigned int smb = (unsigned int)__cvta_generic_to_shared(sm);
    int*   toks = (int*)(sm + OFF_CTRL);
    float* swt  = sm + OFF_CTRL + 128;
    float* bis  = sm + OFF_CTRL + 256;

    int e = blockIdx.z;
    int rows = g_cnt[e];
    int row0 = blockIdx.x * 128;
    if (row0 >= rows) return;
    int h0 = blockIdx.y * 128;

    int tid = threadIdx.x;
    if (tid < 128) {
        int r = row0 + tid;
        toks[tid] = (r < rows) ? g_dtok[e * CAPMAX + r] : -1;
        swt[tid]  = (r < rows) ? g_dwt[e * CAPMAX + r] : 0.f;
        bis[tid]  = b1[e * HH + h0 + tid];
    }
    __syncthreads();

    const __half* w1e = g_w1h + (size_t)e * DD * HH;

    auto fill = [&](int s) {
        int k0 = s * 64;
        unsigned int Ad = smb + (unsigned int)((s % 3) * STG_B);
        unsigned int Bd = Ad + 18432u;
#pragma unroll
        for (int it = 0; it < 4; it++) {           // A: 128 rows x 8 chunks(16B=8 halves)
            int idx = tid + it * 256;
            int r = idx >> 3, c = idx & 7;
            int tok = toks[r];
            cp16(Ad + (unsigned int)(r * 144 + c * 16),
                 g_xh + (size_t)(tok < 0 ? 0 : tok) * DD + k0 + c * 8, tok < 0 ? 0 : 16);
        }
#pragma unroll
        for (int it = 0; it < 4; it++) {           // B: 64 rows x 16 chunks
            int idx = tid + it * 256;
            int kr = idx >> 4, c = idx & 15;
            cp16(Bd + (unsigned int)(kr * 272 + c * 16),
                 w1e + (size_t)(k0 + kr) * HH + h0 + c * 8, 16);
        }
    };

    fill(0); cp_commit();
    fill(1); cp_commit();

    int wid = tid >> 5, wm = wid & 3, wn = wid >> 2;   // warp tile 32(M) x 64(N)
    wmma::fragment<wmma::accumulator, 16, 16, 16, float> acc[2][4];
#pragma unroll
    for (int mi = 0; mi < 2; mi++)
#pragma unroll
        for (int ni = 0; ni < 4; ni++) wmma::fill_fragment(acc[mi][ni], 0.f);

    const int KS = DD / 64;   // 8
    for (int ks = 0; ks < KS; ks++) {
        cp_wait<1>();
        __syncthreads();
        if (ks + 2 < KS) fill(ks + 2);
        cp_commit();
        const __half* Ab = (const __half*)sm + (size_t)(ks % 3) * STG_H;
        const __half* Bb = Ab + 9216;
#pragma unroll
        for (int kk = 0; kk < 4; kk++) {
            wmma::fragment<wmma::matrix_a, 16, 16, 16, __half, wmma::row_major> a[2];
            wmma::fragment<wmma::matrix_b, 16, 16, 16, __half, wmma::row_major> b[4];
            wmma::load_matrix_sync(a[0], Ab + (wm * 32) * A_LDH + kk * 16, A_LDH);
            wmma::load_matrix_sync(a[1], Ab + (wm * 32 + 16) * A_LDH + kk * 16, A_LDH);
#pragma unroll
            for (int ni = 0; ni < 4; ni++)
                wmma::load_matrix_sync(b[ni], Bb + (kk * 16) * B_LDH + wn * 64 + ni * 16, B_LDH);
#pragma unroll
            for (int mi = 0; mi < 2; mi++)
#pragma unroll
                for (int ni = 0; ni < 4; ni++)
                    wmma::mma_sync(acc[mi][ni], a[mi], b[ni], acc[mi][ni]);
        }
    }

    // epilogue: smem roundtrip -> bias + gelu + gate-scale -> fp16 store
    __syncthreads();
    float* Cs = sm;   // [128][136] fp32
#pragma unroll
    for (int mi = 0; mi < 2; mi++)
#pragma unroll
        for (int ni = 0; ni < 4; ni++)
            wmma::store_matrix_sync(Cs + (size_t)(wm * 32 + mi * 16) * 136 + wn * 64 + ni * 16,
                                    acc[mi][ni], 136, wmma::mem_row_major);
    __syncthreads();
    __half* hb = g_hbuf + (size_t)(e * CAPMAX + row0) * HH + h0;
#pragma unroll
    for (int i = 0; i < 32; i++) {
        int idx = tid + i * 256;                   // 128 rows x 64 half2
        int r = idx >> 6, c2 = idx & 63;
        float w = swt[r];
        float v0 = gelu_f(Cs[r * 136 + 2 * c2]     + bis[2 * c2])     * w;
        float v1 = gelu_f(Cs[r * 136 + 2 * c2 + 1] + bis[2 * c2 + 1]) * w;
        ((__half2*)(hb + (size_t)r * HH))[c2] = __floats2half2_rn(v0, v1);
    }
}

// ---------------- kernel 4: GEMM2  ybuf = hbuf @ W2[e] + wt*b2 ----------------
__global__ void __launch_bounds__(256, 2) gemm2_kernel(const float* __restrict__ b2) {
    extern __shared__ float sm[];
    unsigned int smb = (unsigned int)__cvta_generic_to_shared(sm);
    float* swt = sm + OFF_CTRL + 128;
    float* bis = sm + OFF_CTRL + 256;

    int e = blockIdx.z;
    int rows = g_cnt[e];
    int row0 = blockIdx.x * 128;
    if (row0 >= rows) return;
    int d0 = blockIdx.y * 128;

    int tid = threadIdx.x;
    if (tid < 128) {
        int r = row0 + tid;
        swt[tid] = (r < rows) ? g_dwt[e * CAPMAX + r] : 0.f;
        bis[tid] = b2[e * DD + d0 + tid];
    }
    __syncthreads();

    const __half* hbase = g_hbuf + (size_t)(e * CAPMAX + row0) * HH;
    const __half* w2e = g_w2h + (size_t)e * HH * DD;

    auto fill = [&](int s) {
        int k0 = s * 64;
        unsigned int Ad = smb + (unsigned int)((s % 3) * STG_B);
        unsigned int Bd = Ad + 18432u;
#pragma unroll
        for (int it = 0; it < 4; it++) {
            int idx = tid + it * 256;
            int r = idx >> 3, c = idx & 7;
            cp16(Ad + (unsigned int)(r * 144 + c * 16),
                 hbase + (size_t)r * HH + k0 + c * 8, 16);
        }
#pragma unroll
        for (int it = 0; it < 4; it++) {
            int idx = tid + it * 256;
            int kr = idx >> 4, c = idx & 15;
            cp16(Bd + (unsigned int)(kr * 272 + c * 16),
                 w2e + (size_t)(k0 + kr) * DD + d0 + c * 8, 16);
        }
    };

    fill(0); cp_commit();
    fill(1); cp_commit();

    int wid = tid >> 5, wm = wid & 3, wn = wid >> 2;
    wmma::fragment<wmma::accumulator, 16, 16, 16, float> acc[2][4];
#pragma unroll
    for (int mi = 0; mi < 2; mi++)
#pragma unroll
        for (int ni = 0; ni < 4; ni++) wmma::fill_fragment(acc[mi][ni], 0.f);

    const int KS = HH / 64;   // 32
    for (int ks = 0; ks < KS; ks++) {
        cp_wait<1>();
        __syncthreads();
        if (ks + 2 < KS) fill(ks + 2);
        cp_commit();
        const __half* Ab = (const __half*)sm + (size_t)(ks % 3) * STG_H;
        const __half* Bb = Ab + 9216;
#pragma unroll
        for (int kk = 0; kk < 4; kk++) {
            wmma::fragment<wmma::matrix_a, 16, 16, 16, __half, wmma::row_major> a[2];
            wmma::fragment<wmma::matrix_b, 16, 16, 16, __half, wmma::row_major> b[4];
            wmma::load_matrix_sync(a[0], Ab + (wm * 32) * A_LDH + kk * 16, A_LDH);
            wmma::load_matrix_sync(a[1], Ab + (wm * 32 + 16) * A_LDH + kk * 16, A_LDH);
#pragma unroll
            for (int ni = 0; ni < 4; ni++)
                wmma::load_matrix_sync(b[ni], Bb + (kk * 16) * B_LDH + wn * 64 + ni * 16, B_LDH);
#pragma unroll
            for (int mi = 0; mi < 2; mi++)
#pragma unroll
                for (int ni = 0; ni < 4; ni++)
                    wmma::mma_sync(acc[mi][ni], a[mi], b[ni], acc[mi][ni]);
        }
    }

    // epilogue: smem roundtrip -> + wt*b2 -> ybuf fp32
    __syncthreads();
    float* Cs = sm;
#pragma unroll
    for (int mi = 0; mi < 2; mi++)
#pragma unroll
        for (int ni = 0; ni < 4; ni++)
            wmma::store_matrix_sync(Cs + (size_t)(wm * 32 + mi * 16) * 136 + wn * 64 + ni * 16,
                                    acc[mi][ni], 136, wmma::mem_row_major);
    __syncthreads();
    float* yb = g_ybuf + (size_t)(e * CAPMAX + row0) * DD + d0;
#pragma unroll
    for (int i = 0; i < 64; i++) {
        int idx = tid + i * 256;
        int r = idx >> 7, c = idx & 127;
        yb[(size_t)r * DD + c] = Cs[r * 136 + c] + swt[r] * bis[c];
    }
}

// ---------------- kernel 5: gather-combine ----------------
__global__ void __launch_bounds__(256) combine_kernel(float* __restrict__ out) {
    int i = blockIdx.x * 256 + threadIdx.x;
    int t = i >> 7;                    // DD/4 = 128 float4 per token
    int d = i & 127;
    int i0 = g_inv[t], i1 = g_inv[TT + t];
    float4 a = make_float4(0.f, 0.f, 0.f, 0.f), b = a;
    if (i0 >= 0) a = *((const float4*)g_ybuf + (size_t)i0 * 128 + d);
    if (i1 >= 0) b = *((const float4*)g_ybuf + (size_t)i1 * 128 + d);
    ((float4*)out)[i] = make_float4(a.x + b.x, a.y + b.y, a.z + b.z, a.w + b.w);
}

// ---------------- launch ----------------
extern "C" void kernel_launch(void* const* d_in, const int* in_sizes, int n_in,
                              void* d_out, int out_size) {
    const float* x  = (const float*)d_in[0];
    const float* gw = (const float*)d_in[1];
    const float* w1 = (const float*)d_in[2];
    const float* b1 = (const float*)d_in[3];
    const float* w2 = (const float*)d_in[4];
    const float* b2 = (const float*)d_in[5];
    float* out = (float*)d_out;

    cudaFuncSetAttribute(gemm1_kernel, cudaFuncAttributeMaxDynamicSharedMemorySize, GSMEM_BYTES);
    cudaFuncSetAttribute(gemm2_kernel, cudaFuncAttributeMaxDynamicSharedMemorySize, GSMEM_BYTES);

    zero_imp_kernel<<<1, 32>>>();
    router_kernel<<<TT / 8, 256>>>(x, gw);
    scan_kernel<<<1, 1024>>>(out, out_size);
    cvtx_kernel<<<(TT * DD / 8) / 256, 256>>>((const float4*)x);
    cvtw1_kernel<<<((size_t)EE * DD * HH / 8) / 256, 256>>>((const float4*)w1);
    cvtw2_kernel<<<((size_t)EE * HH * DD / 8) / 256, 256>>>((const float4*)w2);
    gemm1_kernel<<<dim3(CAPMAX / 128, HH / 128, EE), 256, GSMEM_BYTES>>>(b1);
    gemm2_kernel<<<dim3(CAPMAX / 128, DD / 128, EE), 256, GSMEM_BYTES>>>(b2);
    combine_kernel<<<(TT * DD / 4) / 256, 256>>>(out);
}

// round 11
// speedup vs baseline: 3.3902x; 1.0593x over previous
#include <cuda_runtime.h>
#include <cuda_fp16.h>
#include <cstdint>
#include <mma.h>
#include <math.h>

using namespace nvcuda;

#define TT 4096
#define DD 512
#define HH 2048
#define EE 8
#define CAP 1075          // round(2*4096*1.05/8)
#define CAPMAX 1152       // 9 * 128

// ---------------- static device scratch ----------------
__device__ float g_imp[EE];
__device__ int   g_ti[2 * TT];
__device__ float g_tg[2 * TT];
__device__ int   g_cnt[EE];
__device__ int   g_dtok[EE * CAPMAX];
__device__ float g_dwt[EE * CAPMAX];
__device__ int   g_inv[2 * TT];
__device__ __align__(16) __half g_xh [(size_t)TT * DD];             // fp16 x       [T][D]
__device__ __align__(16) __half g_w1h[(size_t)EE * DD * HH];        // fp16 W1      [E][D][H]
__device__ __align__(16) __half g_w2h[(size_t)EE * HH * DD];        // fp16 W2      [E][H][D]
__device__ __align__(16) __half g_hbuf[(size_t)EE * CAPMAX * HH];   // fp16 wt*gelu(h)
__device__ __align__(16) float  g_ybuf[(size_t)EE * CAPMAX * DD];

__device__ __forceinline__ float gelu_f(float v) {
    return 0.5f * v * (1.f + erff(v * 0.7071067811865476f));
}
__device__ __forceinline__ void cp16(unsigned int dst, const void* src, int sz) {
    asm volatile("cp.async.cg.shared.global [%0], [%1], 16, %2;"
                 :: "r"(dst), "l"(src), "r"(sz));
}
__device__ __forceinline__ void cp_commit() { asm volatile("cp.async.commit_group;"); }
template<int N> __device__ __forceinline__ void cp_wait() {
    asm volatile("cp.async.wait_group %0;" :: "n"(N));
}
__device__ __forceinline__ uint4 pack8h(float4 v0, float4 v1) {
    __half2 p0 = __floats2half2_rn(v0.x, v0.y);
    __half2 p1 = __floats2half2_rn(v0.z, v0.w);
    __half2 p2 = __floats2half2_rn(v1.x, v1.y);
    __half2 p3 = __floats2half2_rn(v1.z, v1.w);
    uint4 o;
    o.x = *reinterpret_cast<unsigned*>(&p0);
    o.y = *reinterpret_cast<unsigned*>(&p1);
    o.z = *reinterpret_cast<unsigned*>(&p2);
    o.w = *reinterpret_cast<unsigned*>(&p3);
    return o;
}

// ---------------- fp16 pre-convert kernels (RN, 4x grid-stride for MLP) ----------------
__global__ void cvtx_kernel(const float4* __restrict__ s) {
    const int NT = 256 * 256;
    int t = blockIdx.x * 256 + threadIdx.x;
#pragma unroll
    for (int k = 0; k < 4; k++) {
        size_t i = (size_t)t + (size_t)k * NT;
        ((uint4*)g_xh)[i] = pack8h(s[2 * i], s[2 * i + 1]);
    }
}
__global__ void cvtw1_kernel(const float4* __restrict__ s) {
    const int NT = 1024 * 256;
    int t = blockIdx.x * 256 + threadIdx.x;
#pragma unroll
    for (int k = 0; k < 4; k++) {
        size_t i = (size_t)t + (size_t)k * NT;
        ((uint4*)g_w1h)[i] = pack8h(s[2 * i], s[2 * i + 1]);
    }
}
__global__ void cvtw2_kernel(const float4* __restrict__ s) {
    const int NT = 1024 * 256;
    int t = blockIdx.x * 256 + threadIdx.x;
#pragma unroll
    for (int k = 0; k < 4; k++) {
        size_t i = (size_t)t + (size_t)k * NT;
        ((uint4*)g_w2h)[i] = pack8h(s[2 * i], s[2 * i + 1]);
    }
}

// ---------------- kernel 0 ----------------
__global__ void zero_imp_kernel() {
    if (threadIdx.x < EE) g_imp[threadIdx.x] = 0.f;
}

// ---------------- kernel 1: router ----------------
__global__ void __launch_bounds__(256) router_kernel(const float* __restrict__ x,
                                                     const float* __restrict__ gw) {
    __shared__ float sgw[EE * DD];
    int tid = threadIdx.x;
    for (int i = tid; i < EE * DD / 4; i += 256)
        ((float4*)sgw)[i] = ((const float4*)gw)[i];
    __syncthreads();

    int wid = tid >> 5, lane = tid & 31;
    int t = blockIdx.x * 8 + wid;
    const float* xr = x + (size_t)t * DD;

    float acc[EE];
#pragma unroll
    for (int e = 0; e < EE; e++) acc[e] = 0.f;
#pragma unroll
    for (int i = 0; i < DD / 32; i++) {
        int d = lane + i * 32;
        float xv = xr[d];
#pragma unroll
        for (int e = 0; e < EE; e++) acc[e] = fmaf(xv, sgw[e * DD + d], acc[e]);
    }
#pragma unroll
    for (int e = 0; e < EE; e++) {
#pragma unroll
        for (int o = 16; o > 0; o >>= 1)
            acc[e] += __shfl_xor_sync(0xffffffffu, acc[e], o);
    }
    if (lane == 0) {
        float mx = acc[0];
#pragma unroll
        for (int e = 1; e < EE; e++) mx = fmaxf(mx, acc[e]);
        float g[EE], s = 0.f;
#pragma unroll
        for (int e = 0; e < EE; e++) { g[e] = expf(acc[e] - mx); s += g[e]; }
        float inv = 1.f / s;
#pragma unroll
        for (int e = 0; e < EE; e++) { g[e] *= inv; atomicAdd(&g_imp[e], g[e]); }
        int i0 = 0; float g0 = g[0];
#pragma unroll
        for (int e = 1; e < EE; e++) if (g[e] > g0) { g0 = g[e]; i0 = e; }
        int i1 = -1; float g1 = -1.f;
#pragma unroll
        for (int e = 0; e < EE; e++) if (e != i0 && g[e] > g1) { g1 = g[e]; i1 = e; }
        g_ti[t] = i0;        g_ti[TT + t] = i1;
        g_tg[t] = g0;        g_tg[TT + t] = g1;
    }
}

// ---------------- kernel 2: slot-major capacity scan + losses ----------------
__global__ void __launch_bounds__(1024) scan_kernel(float* __restrict__ out, int out_size) {
    int i = threadIdx.x;
    int myexp[8];
    unsigned long long c0 = 0, c1 = 0;
#pragma unroll
    for (int u = 0; u < 8; u++) {
        int j = i * 8 + u;
        int e = g_ti[j];
        myexp[u] = e;
        if (e < 4) c0 += 1ULL << (16 * e); else c1 += 1ULL << (16 * (e - 4));
    }
    __shared__ unsigned long long sA[1024], sB[1024];
    sA[i] = c0; sB[i] = c1;
    __syncthreads();
    for (int off = 1; off < 1024; off <<= 1) {
        unsigned long long a = 0, b = 0;
        if (i >= off) { a = sA[i - off]; b = sB[i - off]; }
        __syncthreads();
        sA[i] += a; sB[i] += b;
        __syncthreads();
    }
    unsigned long long e0 = sA[i] - c0, e1 = sB[i] - c1;
    int run[8];
#pragma unroll
    for (int e = 0; e < 4; e++) {
        run[e]     = (int)((e0 >> (16 * e)) & 0xFFFF);
        run[e + 4] = (int)((e1 >> (16 * e)) & 0xFFFF);
    }
#pragma unroll
    for (int u = 0; u < 8; u++) {
        int j = i * 8 + u;
        int e = myexp[u];
        int pos = run[e]++;
        if (pos < CAP) {
            int o = e * CAPMAX + pos;
            g_dtok[o] = j & (TT - 1);
            g_dwt[o]  = g_tg[j];
            g_inv[j]  = o;
        } else {
            g_inv[j] = -1;
        }
    }
    if (i == 1023) {
        unsigned long long t0 = sA[1023], t1 = sB[1023];
        float tpe[8];
        for (int e = 0; e < 4; e++) {
            int a = min((int)((t0 >> (16 * e)) & 0xFFFF), CAP);
            int b = min((int)((t1 >> (16 * e)) & 0xFFFF), CAP);
            g_cnt[e] = a;     tpe[e] = (float)a;
            g_cnt[e + 4] = b; tpe[e + 4] = (float)b;
        }
        double s = 0, ss = 0;
        for (int e = 0; e < 8; e++) { s += tpe[e]; ss += (double)tpe[e] * tpe[e]; }
        double m = s / 8.0, var = ss / 8.0 - m * m; if (var < 0) var = 0;
        double l_load = var / ((m + 1e-6) * (m + 1e-6));
        double s2 = 0, sq2 = 0;
        for (int e = 0; e < 8; e++) { double v = g_imp[e]; s2 += v; sq2 += v * v; }
        double m2 = s2 / 8.0, v2 = sq2 / 8.0 - m2 * m2; if (v2 < 0) v2 = 0;
        double imp_loss = v2 / ((m2 + 1e-6) * (m2 + 1e-6));
        if (out_size >= TT * DD + 2) {
            out[TT * DD]     = (float)(0.5 * (imp_loss + l_load));
            out[TT * DD + 1] = (float)l_load;
        }
    }
}

// ============ fp16 GEMM tiling ============
// Block tile 128x128, 4 warps (2x2), warp tile 64x64, k-slab 32, 4-stage cp.async.
// Stage: A 128x40 halves (10240 B) + B 32x136 halves (8704 B) = 18944 B; x4 = 75776 B.
// Epilogue C tile fp32 128x136 = 69632 B reuses stage area.
#define A_LDH 40
#define B_LDH 136
#define STG_B 18944
#define OFF_CTRL 18944               // floats (= 75776 B)
#define GSMEM_BYTES ((OFF_CTRL + 384) * 4)

// ---------------- kernel 3: GEMM1  hbuf(fp16) = wt * gelu(Xg @ W1[e] + b1[e]) ----------------
__global__ void __launch_bounds__(128, 2) gemm1_kernel(const float* __restrict__ b1) {
    extern __shared__ float sm[];
    unsigned int smb = (unsigned int)__cvta_generic_to_shared(sm);
    int*   toks = (int*)(sm + OFF_CTRL);
    float* swt  = sm + OFF_CTRL + 128;
    float* bis  = sm + OFF_CTRL + 256;

    int e = blockIdx.z;
    int rows = g_cnt[e];
    int row0 = blockIdx.x * 128;
    if (row0 >= rows) return;
    int h0 = blockIdx.y * 128;

    int tid = threadIdx.x;
    {
        int r = row0 + tid;
        toks[tid] = (r < rows) ? g_dtok[e * CAPMAX + tid + row0] : -1;
        swt[tid]  = (r < rows) ? g_dwt[e * CAPMAX + tid + row0] : 0.f;
        bis[tid]  = b1[e * HH + h0 + tid];
    }
    __syncthreads();

    const __half* w1e = g_w1h + (size_t)e * DD * HH;

    auto fill = [&](int s) {
        int k0 = s * 32;
        unsigned int Ad = smb + (unsigned int)((s & 3) * STG_B);
        unsigned int Bd = Ad + 10240u;
#pragma unroll
        for (int it = 0; it < 4; it++) {           // A: 128 rows x 4 chunks (32 halves)
            int idx = tid + it * 128;
            int r = idx >> 2, c = idx & 3;
            int tok = toks[r];
            cp16(Ad + (unsigned int)(r * 80 + c * 16),
                 g_xh + (size_t)(tok < 0 ? 0 : tok) * DD + k0 + c * 8, tok < 0 ? 0 : 16);
        }
#pragma unroll
        for (int it = 0; it < 4; it++) {           // B: 32 rows x 16 chunks (128 halves)
            int idx = tid + it * 128;
            int kr = idx >> 4, c = idx & 15;
            cp16(Bd + (unsigned int)(kr * 272 + c * 16),
                 w1e + (size_t)(k0 + kr) * HH + h0 + c * 8, 16);
        }
    };

    fill(0); cp_commit();
    fill(1); cp_commit();
    fill(2); cp_commit();

    int wid = tid >> 5, wm = wid & 1, wn = wid >> 1;   // warp tile 64(M) x 64(N)
    wmma::fragment<wmma::accumulator, 16, 16, 16, float> acc[4][4];
#pragma unroll
    for (int mi = 0; mi < 4; mi++)
#pragma unroll
        for (int ni = 0; ni < 4; ni++) wmma::fill_fragment(acc[mi][ni], 0.f);

    const int KS = DD / 32;   // 16
    for (int ks = 0; ks < KS; ks++) {
        cp_wait<2>();
        __syncthreads();
        if (ks + 3 < KS) fill(ks + 3);
        cp_commit();
        const __half* Ab = (const __half*)sm + (size_t)(ks & 3) * (STG_B / 2);
        const __half* Bb = Ab + 5120;
#pragma unroll
        for (int kk = 0; kk < 2; kk++) {
            wmma::fragment<wmma::matrix_a, 16, 16, 16, __half, wmma::row_major> a[4];
            wmma::fragment<wmma::matrix_b, 16, 16, 16, __half, wmma::row_major> b[4];
#pragma unroll
            for (int mi = 0; mi < 4; mi++)
                wmma::load_matrix_sync(a[mi], Ab + (wm * 64 + mi * 16) * A_LDH + kk * 16, A_LDH);
#pragma unroll
            for (int ni = 0; ni < 4; ni++)
                wmma::load_matrix_sync(b[ni], Bb + (kk * 16) * B_LDH + wn * 64 + ni * 16, B_LDH);
#pragma unroll
            for (int mi = 0; mi < 4; mi++)
#pragma unroll
                for (int ni = 0; ni < 4; ni++)
                    wmma::mma_sync(acc[mi][ni], a[mi], b[ni], acc[mi][ni]);
        }
    }

    // epilogue: smem roundtrip -> bias + gelu + gate-scale -> fp16 store
    __syncthreads();
    float* Cs = sm;   // [128][136] fp32
#pragma unroll
    for (int mi = 0; mi < 4; mi++)
#pragma unroll
        for (int ni = 0; ni < 4; ni++)
            wmma::store_matrix_sync(Cs + (size_t)(wm * 64 + mi * 16) * 136 + wn * 64 + ni * 16,
                                    acc[mi][ni], 136, wmma::mem_row_major);
    __syncthreads();
    __half* hb = g_hbuf + (size_t)(e * CAPMAX + row0) * HH + h0;
#pragma unroll
    for (int i = 0; i < 64; i++) {
        int idx = tid + i * 128;                   // 128 rows x 64 half2
        int r = idx >> 6, c2 = idx & 63;
        float w = swt[r];
        float v0 = gelu_f(Cs[r * 136 + 2 * c2]     + bis[2 * c2])     * w;
        float v1 = gelu_f(Cs[r * 136 + 2 * c2 + 1] + bis[2 * c2 + 1]) * w;
        ((__half2*)(hb + (size_t)r * HH))[c2] = __floats2half2_rn(v0, v1);
    }
}

// ---------------- kernel 4: GEMM2  ybuf = hbuf @ W2[e] + wt*b2 ----------------
__global__ void __launch_bounds__(128, 2) gemm2_kernel(const float* __restrict__ b2) {
    extern __shared__ float sm[];
    unsigned int smb = (unsigned int)__cvta_generic_to_shared(sm);
    float* swt = sm + OFF_CTRL + 128;
    float* bis = sm + OFF_CTRL + 256;

    int e = blockIdx.z;
    int rows = g_cnt[e];
    int row0 = blockIdx.x * 128;
    if (row0 >= rows) return;
    int d0 = blockIdx.y * 128;

    int tid = threadIdx.x;
    {
        int r = row0 + tid;
        swt[tid] = (r < rows) ? g_dwt[e * CAPMAX + tid + row0] : 0.f;
        bis[tid] = b2[e * DD + d0 + tid];
    }
    __syncthreads();

    const __half* hbase = g_hbuf + (size_t)(e * CAPMAX + row0) * HH;
    const __half* w2e = g_w2h + (size_t)e * HH * DD;

    auto fill = [&](int s) {
        int k0 = s * 32;
        unsigned int Ad = smb + (unsigned int)((s & 3) * STG_B);
        unsigned int Bd = Ad + 10240u;
#pragma unroll
        for (int it = 0; it < 4; it++) {
            int idx = tid + it * 128;
            int r = idx >> 2, c = idx & 3;
            cp16(Ad + (unsigned int)(r * 80 + c * 16),
                 hbase + (size_t)r * HH + k0 + c * 8, 16);
        }
#pragma unroll
        for (int it = 0; it < 4; it++) {
            int idx = tid + it * 128;
            int kr = idx >> 4, c = idx & 15;
            cp16(Bd + (unsigned int)(kr * 272 + c * 16),
                 w2e + (size_t)(k0 + kr) * DD + d0 + c * 8, 16);
        }
    };

    fill(0); cp_commit();
    fill(1); cp_commit();
    fill(2); cp_commit();

    int wid = tid >> 5, wm = wid & 1, wn = wid >> 1;
    wmma::fragment<wmma::accumulator, 16, 16, 16, float> acc[4][4];
#pragma unroll
    for (int mi = 0; mi < 4; mi++)
#pragma unroll
        for (int ni = 0; ni < 4; ni++) wmma::fill_fragment(acc[mi][ni], 0.f);

    const int KS = HH / 32;   // 64
    for (int ks = 0; ks < KS; ks++) {
        cp_wait<2>();
        __syncthreads();
        if (ks + 3 < KS) fill(ks + 3);
        cp_commit();
        const __half* Ab = (const __half*)sm + (size_t)(ks & 3) * (STG_B / 2);
        const __half* Bb = Ab + 5120;
#pragma unroll
        for (int kk = 0; kk < 2; kk++) {
            wmma::fragment<wmma::matrix_a, 16, 16, 16, __half, wmma::row_major> a[4];
            wmma::fragment<wmma::matrix_b, 16, 16, 16, __half, wmma::row_major> b[4];
#pragma unroll
            for (int mi = 0; mi < 4; mi++)
                wmma::load_matrix_sync(a[mi], Ab + (wm * 64 + mi * 16) * A_LDH + kk * 16, A_LDH);
#pragma unroll
            for (int ni = 0; ni < 4; ni++)
                wmma::load_matrix_sync(b[ni], Bb + (kk * 16) * B_LDH + wn * 64 + ni * 16, B_LDH);
#pragma unroll
            for (int mi = 0; mi < 4; mi++)
#pragma unroll
                for (int ni = 0; ni < 4; ni++)
                    wmma::mma_sync(acc[mi][ni], a[mi], b[ni], acc[mi][ni]);
        }
    }

    // epilogue: smem roundtrip -> + wt*b2 -> ybuf fp32
    __syncthreads();
    float* Cs = sm;
#pragma unroll
    for (int mi = 0; mi < 4; mi++)
#pragma unroll
        for (int ni = 0; ni < 4; ni++)
            wmma::store_matrix_sync(Cs + (size_t)(wm * 64 + mi * 16) * 136 + wn * 64 + ni * 16,
                                    acc[mi][ni], 136, wmma::mem_row_major);
    __syncthreads();
    float* yb = g_ybuf + (size_t)(e * CAPMAX + row0) * DD + d0;
#pragma unroll
    for (int i = 0; i < 128; i++) {
        int idx = tid + i * 128;
        int r = idx >> 7, c = idx & 127;
        yb[(size_t)r * DD + c] = Cs[r * 136 + c] + swt[r] * bis[c];
    }
}

// ---------------- kernel 5: gather-combine ----------------
__global__ void __launch_bounds__(256) combine_kernel(float* __restrict__ out) {
    int i = blockIdx.x * 256 + threadIdx.x;
    int t = i >> 7;                    // DD/4 = 128 float4 per token
    int d = i & 127;
    int i0 = g_inv[t], i1 = g_inv[TT + t];
    float4 a = make_float4(0.f, 0.f, 0.f, 0.f), b = a;
    if (i0 >= 0) a = *((const float4*)g_ybuf + (size_t)i0 * 128 + d);
    if (i1 >= 0) b = *((const float4*)g_ybuf + (size_t)i1 * 128 + d);
    ((float4*)out)[i] = make_float4(a.x + b.x, a.y + b.y, a.z + b.z, a.w + b.w);
}

// ---------------- launch ----------------
extern "C" void kernel_launch(void* const* d_in, const int* in_sizes, int n_in,
                              void* d_out, int out_size) {
    const float* x  = (const float*)d_in[0];
    const float* gw = (const float*)d_in[1];
    const float* w1 = (const float*)d_in[2];
    const float* b1 = (const float*)d_in[3];
    const float* w2 = (const float*)d_in[4];
    const float* b2 = (const float*)d_in[5];
    float* out = (float*)d_out;

    cudaFuncSetAttribute(gemm1_kernel, cudaFuncAttributeMaxDynamicSharedMemorySize, GSMEM_BYTES);
    cudaFuncSetAttribute(gemm2_kernel, cudaFuncAttributeMaxDynamicSharedMemorySize, GSMEM_BYTES);

    // order arranged so gemm1 is the 6th launch (ncu -s 5 -c 1 captures it)
    cvtx_kernel<<<256, 256>>>((const float4*)x);
    cvtw1_kernel<<<1024, 256>>>((const float4*)w1);
    zero_imp_kernel<<<1, 32>>>();
    router_kernel<<<TT / 8, 256>>>(x, gw);
    scan_kernel<<<1, 1024>>>(out, out_size);
    gemm1_kernel<<<dim3(CAPMAX / 128, HH / 128, EE), 128, GSMEM_BYTES>>>(b1);
    cvtw2_kernel<<<1024, 256>>>((const float4*)w2);
    gemm2_kernel<<<dim3(CAPMAX / 128, DD / 128, EE), 128, GSMEM_BYTES>>>(b2);
    combine_kernel<<<(TT * DD / 4) / 256, 256>>>(out);
}

// round 12
// speedup vs baseline: 4.3060x; 1.2702x over previous
#include <cuda_runtime.h>
#include <cuda_fp16.h>
#include <cstdint>
#include <mma.h>
#include <math.h>

using namespace nvcuda;

#define TT 4096
#define DD 512
#define HH 2048
#define EE 8
#define CAP 1075          // round(2*4096*1.05/8)
#define CAPMAX 1152       // 9 * 128

typedef unsigned long long u64;

// ---------------- static device scratch ----------------
__device__ float g_imp[EE];
__device__ int   g_ti[2 * TT];
__device__ float g_tg[2 * TT];
__device__ int   g_cnt[EE];
__device__ int   g_dtok[EE * CAPMAX];
__device__ float g_dwt[EE * CAPMAX];
__device__ int   g_inv[2 * TT];
__device__ __align__(16) __half g_xh [(size_t)TT * DD];             // fp16 x (written by router)
__device__ __align__(16) __half g_w1h[(size_t)EE * DD * HH];        // fp16 W1
__device__ __align__(16) __half g_w2h[(size_t)EE * HH * DD];        // fp16 W2
__device__ __align__(16) __half g_hbuf[(size_t)EE * CAPMAX * HH];   // fp16 wt*gelu(h)
__device__ __align__(16) float  g_ybuf[(size_t)EE * CAPMAX * DD];

__device__ __forceinline__ float gelu_f(float v) {
    return 0.5f * v * (1.f + erff(v * 0.7071067811865476f));
}
__device__ __forceinline__ void cp16(unsigned int dst, const void* src, int sz) {
    asm volatile("cp.async.cg.shared.global [%0], [%1], 16, %2;"
                 :: "r"(dst), "l"(src), "r"(sz));
}
__device__ __forceinline__ void cp_commit() { asm volatile("cp.async.commit_group;"); }
template<int N> __device__ __forceinline__ void cp_wait() {
    asm volatile("cp.async.wait_group %0;" :: "n"(N));
}
__device__ __forceinline__ uint4 pack8h(float4 v0, float4 v1) {
    __half2 p0 = __floats2half2_rn(v0.x, v0.y);
    __half2 p1 = __floats2half2_rn(v0.z, v0.w);
    __half2 p2 = __floats2half2_rn(v1.x, v1.y);
    __half2 p3 = __floats2half2_rn(v1.z, v1.w);
    uint4 o;
    o.x = *reinterpret_cast<unsigned*>(&p0);
    o.y = *reinterpret_cast<unsigned*>(&p1);
    o.z = *reinterpret_cast<unsigned*>(&p2);
    o.w = *reinterpret_cast<unsigned*>(&p3);
    return o;
}

// ---------------- fp16 weight pre-convert (RN, 4x grid-stride) ----------------
__global__ void cvtw1_kernel(const float4* __restrict__ s) {
    const int NT = 1024 * 256;
    int t = blockIdx.x * 256 + threadIdx.x;
#pragma unroll
    for (int k = 0; k < 4; k++) {
        size_t i = (size_t)t + (size_t)k * NT;
        ((uint4*)g_w1h)[i] = pack8h(s[2 * i], s[2 * i + 1]);
    }
}
__global__ void cvtw2_kernel(const float4* __restrict__ s) {
    const int NT = 1024 * 256;
    int t = blockIdx.x * 256 + threadIdx.x;
#pragma unroll
    for (int k = 0; k < 4; k++) {
        size_t i = (size_t)t + (size_t)k * NT;
        ((uint4*)g_w2h)[i] = pack8h(s[2 * i], s[2 * i + 1]);
    }
}

// ---------------- kernel 0 ----------------
__global__ void zero_imp_kernel() {
    if (threadIdx.x < EE) g_imp[threadIdx.x] = 0.f;
}

// ---------------- kernel 1: router (float4 MLP, fused fp16-x emit, staged imp) ----------------
__global__ void __launch_bounds__(256) router_kernel(const float4* __restrict__ x4,
                                                     const float4* __restrict__ gw4) {
    __shared__ float4 sgw[EE * 128];
    __shared__ float  simp[EE];
    int tid = threadIdx.x;
    for (int i = tid; i < EE * 128; i += 256) sgw[i] = gw4[i];
    if (tid < EE) simp[tid] = 0.f;
    __syncthreads();

    int wid = tid >> 5, lane = tid & 31;
    int t = blockIdx.x * 8 + wid;
    const float4* xr = x4 + (size_t)t * 128;

    float4 xv[4];
#pragma unroll
    for (int i = 0; i < 4; i++) xv[i] = xr[lane + 32 * i];   // 4 independent LDG.128

    // emit fp16 copy of x
    uint2* xh = (uint2*)(g_xh + (size_t)t * DD);
#pragma unroll
    for (int i = 0; i < 4; i++) {
        __half2 lo = __floats2half2_rn(xv[i].x, xv[i].y);
        __half2 hi = __floats2half2_rn(xv[i].z, xv[i].w);
        uint2 u;
        u.x = *reinterpret_cast<unsigned*>(&lo);
        u.y = *reinterpret_cast<unsigned*>(&hi);
        xh[lane + 32 * i] = u;
    }

    float acc[EE];
#pragma unroll
    for (int e = 0; e < EE; e++) acc[e] = 0.f;
#pragma unroll
    for (int i = 0; i < 4; i++) {
#pragma unroll
        for (int e = 0; e < EE; e++) {
            float4 w = sgw[e * 128 + lane + 32 * i];
            acc[e] = fmaf(xv[i].x, w.x, fmaf(xv[i].y, w.y,
                     fmaf(xv[i].z, w.z, fmaf(xv[i].w, w.w, acc[e]))));
        }
    }
#pragma unroll
    for (int e = 0; e < EE; e++) {
#pragma unroll
        for (int o = 16; o > 0; o >>= 1)
            acc[e] += __shfl_xor_sync(0xffffffffu, acc[e], o);
    }
    if (lane == 0) {
        float mx = acc[0];
#pragma unroll
        for (int e = 1; e < EE; e++) mx = fmaxf(mx, acc[e]);
        float g[EE], s = 0.f;
#pragma unroll
        for (int e = 0; e < EE; e++) { g[e] = expf(acc[e] - mx); s += g[e]; }
        float inv = 1.f / s;
#pragma unroll
        for (int e = 0; e < EE; e++) { g[e] *= inv; atomicAdd(&simp[e], g[e]); }
        int i0 = 0; float g0 = g[0];
#pragma unroll
        for (int e = 1; e < EE; e++) if (g[e] > g0) { g0 = g[e]; i0 = e; }
        int i1 = -1; float g1 = -1.f;
#pragma unroll
        for (int e = 0; e < EE; e++) if (e != i0 && g[e] > g1) { g1 = g[e]; i1 = e; }
        g_ti[t] = i0;        g_ti[TT + t] = i1;
        g_tg[t] = g0;        g_tg[TT + t] = g1;
    }
    __syncthreads();
    if (tid < EE) atomicAdd(&g_imp[tid], simp[tid]);
}

// ---------------- kernel 2: slot-major capacity scan (shuffle-based) + losses ----------------
__global__ void __launch_bounds__(1024) scan_kernel(float* __restrict__ out, int out_size) {
    int i = threadIdx.x, lane = i & 31, wid = i >> 5;
    int myexp[8];
    u64 c0 = 0, c1 = 0;
#pragma unroll
    for (int u = 0; u < 8; u++) {
        int j = i * 8 + u;
        int e = g_ti[j];
        myexp[u] = e;
        if (e < 4) c0 += 1ULL << (16 * e); else c1 += 1ULL << (16 * (e - 4));
    }
    // warp inclusive scan
    u64 s0 = c0, s1 = c1;
#pragma unroll
    for (int off = 1; off < 32; off <<= 1) {
        u64 a = __shfl_up_sync(0xffffffffu, s0, off);
        u64 b = __shfl_up_sync(0xffffffffu, s1, off);
        if (lane >= off) { s0 += a; s1 += b; }
    }
    __shared__ u64 w0[32], w1[32];
    if (lane == 31) { w0[wid] = s0; w1[wid] = s1; }
    __syncthreads();
    if (wid == 0) {
        u64 a0 = w0[lane], a1 = w1[lane];
        __syncwarp();
#pragma unroll
        for (int off = 1; off < 32; off <<= 1) {
            u64 a = __shfl_up_sync(0xffffffffu, a0, off);
            u64 b = __shfl_up_sync(0xffffffffu, a1, off);
            if (lane >= off) { a0 += a; a1 += b; }
        }
        w0[lane] = a0; w1[lane] = a1;    // inclusive warp prefix
    }
    __syncthreads();
    u64 off0 = (wid > 0) ? w0[wid - 1] : 0;
    u64 off1 = (wid > 0) ? w1[wid - 1] : 0;
    u64 inc0 = s0 + off0, inc1 = s1 + off1;    // inclusive incl. own
    u64 e0 = inc0 - c0, e1 = inc1 - c1;        // exclusive prefix
    int run[8];
#pragma unroll
    for (int e = 0; e < 4; e++) {
        run[e]     = (int)((e0 >> (16 * e)) & 0xFFFF);
        run[e + 4] = (int)((e1 >> (16 * e)) & 0xFFFF);
    }
#pragma unroll
    for (int u = 0; u < 8; u++) {
        int j = i * 8 + u;
        int e = myexp[u];
        int pos = run[e]++;
        if (pos < CAP) {
            int o = e * CAPMAX + pos;
            g_dtok[o] = j & (TT - 1);
            g_dwt[o]  = g_tg[j];
            g_inv[j]  = o;
        } else {
            g_inv[j] = -1;
        }
    }
    if (i == 1023) {
        u64 t0 = inc0, t1 = inc1;       // grand totals
        float tpe[8];
        for (int e = 0; e < 4; e++) {
            int a = min((int)((t0 >> (16 * e)) & 0xFFFF), CAP);
            int b = min((int)((t1 >> (16 * e)) & 0xFFFF), CAP);
            g_cnt[e] = a;     tpe[e] = (float)a;
            g_cnt[e + 4] = b; tpe[e + 4] = (float)b;
        }
        double s = 0, ss = 0;
        for (int e = 0; e < 8; e++) { s += tpe[e]; ss += (double)tpe[e] * tpe[e]; }
        double m = s / 8.0, var = ss / 8.0 - m * m; if (var < 0) var = 0;
        double l_load = var / ((m + 1e-6) * (m + 1e-6));
        double s2 = 0, sq2 = 0;
        for (int e = 0; e < 8; e++) { double v = g_imp[e]; s2 += v; sq2 += v * v; }
        double m2 = s2 / 8.0, v2 = sq2 / 8.0 - m2 * m2; if (v2 < 0) v2 = 0;
        double imp_loss = v2 / ((m2 + 1e-6) * (m2 + 1e-6));
        if (out_size >= TT * DD + 2) {
            out[TT * DD]     = (float)(0.5 * (imp_loss + l_load));
            out[TT * DD + 1] = (float)l_load;
        }
    }
}

// ============ fp16 GEMM tiling ============
// Block tile 128x128, 4 warps (2x2), warp tile 64x64, k-slab 32, 4-stage cp.async.
#define A_LDH 40
#define B_LDH 136
#define STG_B 18944
#define OFF_CTRL 18944               // floats (= 75776 B)
#define GSMEM_BYTES ((OFF_CTRL + 384) * 4)

// ---------------- kernel 3: GEMM1  hbuf(fp16) = wt * gelu(Xg @ W1[e] + b1[e]) ----------------
__global__ void __launch_bounds__(128, 2) gemm1_kernel(const float* __restrict__ b1) {
    extern __shared__ float sm[];
    unsigned int smb = (unsigned int)__cvta_generic_to_shared(sm);
    int*   toks = (int*)(sm + OFF_CTRL);
    float* swt  = sm + OFF_CTRL + 128;
    float* bis  = sm + OFF_CTRL + 256;

    int e = blockIdx.z;
    int rows = g_cnt[e];
    int row0 = blockIdx.x * 128;
    if (row0 >= rows) return;
    int h0 = blockIdx.y * 128;

    int tid = threadIdx.x;
    {
        int r = row0 + tid;
        toks[tid] = (r < rows) ? g_dtok[e * CAPMAX + r] : -1;
        swt[tid]  = (r < rows) ? g_dwt[e * CAPMAX + r] : 0.f;
        bis[tid]  = b1[e * HH + h0 + tid];
    }
    __syncthreads();

    const __half* w1e = g_w1h + (size_t)e * DD * HH;

    auto fill = [&](int s) {
        int k0 = s * 32;
        unsigned int Ad = smb + (unsigned int)((s & 3) * STG_B);
        unsigned int Bd = Ad + 10240u;
#pragma unroll
        for (int it = 0; it < 4; it++) {
            int idx = tid + it * 128;
            int r = idx >> 2, c = idx & 3;
            int tok = toks[r];
            cp16(Ad + (unsigned int)(r * 80 + c * 16),
                 g_xh + (size_t)(tok < 0 ? 0 : tok) * DD + k0 + c * 8, tok < 0 ? 0 : 16);
        }
#pragma unroll
        for (int it = 0; it < 4; it++) {
            int idx = tid + it * 128;
            int kr = idx >> 4, c = idx & 15;
            cp16(Bd + (unsigned int)(kr * 272 + c * 16),
                 w1e + (size_t)(k0 + kr) * HH + h0 + c * 8, 16);
        }
    };

    fill(0); cp_commit();
    fill(1); cp_commit();
    fill(2); cp_commit();

    int wid = tid >> 5, wm = wid & 1, wn = wid >> 1;   // warp tile 64x64
    wmma::fragment<wmma::accumulator, 16, 16, 16, float> acc[4][4];
#pragma unroll
    for (int mi = 0; mi < 4; mi++)
#pragma unroll
        for (int ni = 0; ni < 4; ni++) wmma::fill_fragment(acc[mi][ni], 0.f);

    const int KS = DD / 32;   // 16
    for (int ks = 0; ks < KS; ks++) {
        cp_wait<2>();
        __syncthreads();
        if (ks + 3 < KS) fill(ks + 3);
        cp_commit();
        const __half* Ab = (const __half*)sm + (size_t)(ks & 3) * (STG_B / 2);
        const __half* Bb = Ab + 5120;
#pragma unroll
        for (int kk = 0; kk < 2; kk++) {
            wmma::fragment<wmma::matrix_a, 16, 16, 16, __half, wmma::row_major> a[4];
            wmma::fragment<wmma::matrix_b, 16, 16, 16, __half, wmma::row_major> b[4];
#pragma unroll
            for (int mi = 0; mi < 4; mi++)
                wmma::load_matrix_sync(a[mi], Ab + (wm * 64 + mi * 16) * A_LDH + kk * 16, A_LDH);
#pragma unroll
            for (int ni = 0; ni < 4; ni++)
                wmma::load_matrix_sync(b[ni], Bb + (kk * 16) * B_LDH + wn * 64 + ni * 16, B_LDH);
#pragma unroll
            for (int mi = 0; mi < 4; mi++)
#pragma unroll
                for (int ni = 0; ni < 4; ni++)
                    wmma::mma_sync(acc[mi][ni], a[mi], b[ni], acc[mi][ni]);
        }
    }

    __syncthreads();
    float* Cs = sm;   // [128][136] fp32
#pragma unroll
    for (int mi = 0; mi < 4; mi++)
#pragma unroll
        for (int ni = 0; ni < 4; ni++)
            wmma::store_matrix_sync(Cs + (size_t)(wm * 64 + mi * 16) * 136 + wn * 64 + ni * 16,
                                    acc[mi][ni], 136, wmma::mem_row_major);
    __syncthreads();
    __half* hb = g_hbuf + (size_t)(e * CAPMAX + row0) * HH + h0;
#pragma unroll
    for (int i = 0; i < 64; i++) {
        int idx = tid + i * 128;
        int r = idx >> 6, c2 = idx & 63;
        float w = swt[r];
        float v0 = gelu_f(Cs[r * 136 + 2 * c2]     + bis[2 * c2])     * w;
        float v1 = gelu_f(Cs[r * 136 + 2 * c2 + 1] + bis[2 * c2 + 1]) * w;
        ((__half2*)(hb + (size_t)r * HH))[c2] = __floats2half2_rn(v0, v1);
    }
}

// ---------------- kernel 4: GEMM2  ybuf = hbuf @ W2[e] + wt*b2 ----------------
__global__ void __launch_bounds__(128, 2) gemm2_kernel(const float* __restrict__ b2) {
    extern __shared__ float sm[];
    unsigned int smb = (unsigned int)__cvta_generic_to_shared(sm);
    float* swt = sm + OFF_CTRL + 128;
    float* bis = sm + OFF_CTRL + 256;

    int e = blockIdx.z;
    int rows = g_cnt[e];
    int row0 = blockIdx.x * 128;
    if (row0 >= rows) return;
    int d0 = blockIdx.y * 128;

    int tid = threadIdx.x;
    {
        int r = row0 + tid;
        swt[tid] = (r < rows) ? g_dwt[e * CAPMAX + r] : 0.f;
        bis[tid] = b2[e * DD + d0 + tid];
    }
    __syncthreads();

    const __half* hbase = g_hbuf + (size_t)(e * CAPMAX + row0) * HH;
    const __half* w2e = g_w2h + (size_t)e * HH * DD;

    auto fill = [&](int s) {
        int k0 = s * 32;
        unsigned int Ad = smb + (unsigned int)((s & 3) * STG_B);
        unsigned int Bd = Ad + 10240u;
#pragma unroll
        for (int it = 0; it < 4; it++) {
            int idx = tid + it * 128;
            int r = idx >> 2, c = idx & 3;
            cp16(Ad + (unsigned int)(r * 80 + c * 16),
                 hbase + (size_t)r * HH + k0 + c * 8, 16);
        }
#pragma unroll
        for (int it = 0; it < 4; it++) {
            int idx = tid + it * 128;
            int kr = idx >> 4, c = idx & 15;
            cp16(Bd + (unsigned int)(kr * 272 + c * 16),
                 w2e + (size_t)(k0 + kr) * DD + d0 + c * 8, 16);
        }
    };

    fill(0); cp_commit();
    fill(1); cp_commit();
    fill(2); cp_commit();

    int wid = tid >> 5, wm = wid & 1, wn = wid >> 1;
    wmma::fragment<wmma::accumulator, 16, 16, 16, float> acc[4][4];
#pragma unroll
    for (int mi = 0; mi < 4; mi++)
#pragma unroll
        for (int ni = 0; ni < 4; ni++) wmma::fill_fragment(acc[mi][ni], 0.f);

    const int KS = HH / 32;   // 64
    for (int ks = 0; ks < KS; ks++) {
        cp_wait<2>();
        __syncthreads();
        if (ks + 3 < KS) fill(ks + 3);
        cp_commit();
        const __half* Ab = (const __half*)sm + (size_t)(ks & 3) * (STG_B / 2);
        const __half* Bb = Ab + 5120;
#pragma unroll
        for (int kk = 0; kk < 2; kk++) {
            wmma::fragment<wmma::matrix_a, 16, 16, 16, __half, wmma::row_major> a[4];
            wmma::fragment<wmma::matrix_b, 16, 16, 16, __half, wmma::row_major> b[4];
#pragma unroll
            for (int mi = 0; mi < 4; mi++)
                wmma::load_matrix_sync(a[mi], Ab + (wm * 64 + mi * 16) * A_LDH + kk * 16, A_LDH);
#pragma unroll
            for (int ni = 0; ni < 4; ni++)
                wmma::load_matrix_sync(b[ni], Bb + (kk * 16) * B_LDH + wn * 64 + ni * 16, B_LDH);
#pragma unroll
            for (int mi = 0; mi < 4; mi++)
#pragma unroll
                for (int ni = 0; ni < 4; ni++)
                    wmma::mma_sync(acc[mi][ni], a[mi], b[ni], acc[mi][ni]);
        }
    }

    __syncthreads();
    float* Cs = sm;
#pragma unroll
    for (int mi = 0; mi < 4; mi++)
#pragma unroll
        for (int ni = 0; ni < 4; ni++)
            wmma::store_matrix_sync(Cs + (size_t)(wm * 64 + mi * 16) * 136 + wn * 64 + ni * 16,
                                    acc[mi][ni], 136, wmma::mem_row_major);
    __syncthreads();
    float* yb = g_ybuf + (size_t)(e * CAPMAX + row0) * DD + d0;
#pragma unroll
    for (int i = 0; i < 128; i++) {
        int idx = tid + i * 128;
        int r = idx >> 7, c = idx & 127;
        yb[(size_t)r * DD + c] = Cs[r * 136 + c] + swt[r] * bis[c];
    }
}

// ---------------- kernel 5: gather-combine ----------------
__global__ void __launch_bounds__(256) combine_kernel(float* __restrict__ out) {
    int i = blockIdx.x * 256 + threadIdx.x;
    int t = i >> 7;
    int d = i & 127;
    int i0 = g_inv[t], i1 = g_inv[TT + t];
    float4 a = make_float4(0.f, 0.f, 0.f, 0.f), b = a;
    if (i0 >= 0) a = *((const float4*)g_ybuf + (size_t)i0 * 128 + d);
    if (i1 >= 0) b = *((const float4*)g_ybuf + (size_t)i1 * 128 + d);
    ((float4*)out)[i] = make_float4(a.x + b.x, a.y + b.y, a.z + b.z, a.w + b.w);
}

// ---------------- launch ----------------
extern "C" void kernel_launch(void* const* d_in, const int* in_sizes, int n_in,
                              void* d_out, int out_size) {
    const float* x  = (const float*)d_in[0];
    const float* gw = (const float*)d_in[1];
    const float* w1 = (const float*)d_in[2];
    const float* b1 = (const float*)d_in[3];
    const float* w2 = (const float*)d_in[4];
    const float* b2 = (const float*)d_in[5];
    float* out = (float*)d_out;

    cudaFuncSetAttribute(gemm1_kernel, cudaFuncAttributeMaxDynamicSharedMemorySize, GSMEM_BYTES);
    cudaFuncSetAttribute(gemm2_kernel, cudaFuncAttributeMaxDynamicSharedMemorySize, GSMEM_BYTES);

    // gemm1 kept as 6th launch so ncu -s 5 -c 1 captures it
    cvtw1_kernel<<<1024, 256>>>((const float4*)w1);
    zero_imp_kernel<<<1, 32>>>();
    router_kernel<<<TT / 8, 256>>>((const float4*)x, (const float4*)gw);
    scan_kernel<<<1, 1024>>>(out, out_size);
    cvtw2_kernel<<<1024, 256>>>((const float4*)w2);
    gemm1_kernel<<<dim3(CAPMAX / 128, HH / 128, EE), 128, GSMEM_BYTES>>>(b1);
    gemm2_kernel<<<dim3(CAPMAX / 128, DD / 128, EE), 128, GSMEM_BYTES>>>(b2);
    combine_kernel<<<(TT * DD / 4) / 256, 256>>>(out);
}

// round 13
// speedup vs baseline: 4.6708x; 1.0847x over previous
#include <cuda_runtime.h>
#include <cuda_fp16.h>
#include <cstdint>
#include <mma.h>
#include <math.h>

using namespace nvcuda;

#define TT 4096
#define DD 512
#define HH 2048
#define EE 8
#define CAP 1075          // round(2*4096*1.05/8)
#define CAPMAX 1152       // 9 * 128

// ---------------- static device scratch ----------------
__device__ float g_imp[EE];
__device__ int   g_ti[2 * TT];
__device__ float g_tg[2 * TT];
__device__ int   g_cnt[EE];
__device__ int   g_chcnt[32 * EE];          // per-chunk (256 slot-major entries) expert counts
__device__ int   g_dtok[EE * CAPMAX];
__device__ float g_dwt[EE * CAPMAX];
__device__ int   g_inv[2 * TT];
__device__ __align__(16) __half g_xh [(size_t)TT * DD];             // fp16 x (written by router)
__device__ __align__(16) __half g_w1h[(size_t)EE * DD * HH];        // fp16 W1
__device__ __align__(16) __half g_w2h[(size_t)EE * HH * DD];        // fp16 W2
__device__ __align__(16) __half g_hbuf[(size_t)EE * CAPMAX * HH];   // fp16 wt*gelu(h)
__device__ __align__(16) float  g_ybuf[(size_t)EE * CAPMAX * DD];

__device__ __forceinline__ float gelu_f(float v) {
    return 0.5f * v * (1.f + erff(v * 0.7071067811865476f));
}
__device__ __forceinline__ void cp16(unsigned int dst, const void* src, int sz) {
    asm volatile("cp.async.cg.shared.global [%0], [%1], 16, %2;"
                 :: "r"(dst), "l"(src), "r"(sz));
}
__device__ __forceinline__ void cp_commit() { asm volatile("cp.async.commit_group;"); }
template<int N> __device__ __forceinline__ void cp_wait() {
    asm volatile("cp.async.wait_group %0;" :: "n"(N));
}
__device__ __forceinline__ uint4 pack8h(float4 v0, float4 v1) {
    __half2 p0 = __floats2half2_rn(v0.x, v0.y);
    __half2 p1 = __floats2half2_rn(v0.z, v0.w);
    __half2 p2 = __floats2half2_rn(v1.x, v1.y);
    __half2 p3 = __floats2half2_rn(v1.z, v1.w);
    uint4 o;
    o.x = *reinterpret_cast<unsigned*>(&p0);
    o.y = *reinterpret_cast<unsigned*>(&p1);
    o.z = *reinterpret_cast<unsigned*>(&p2);
    o.w = *reinterpret_cast<unsigned*>(&p3);
    return o;
}

// ---------------- kernel 1: cvtw1 + zero-init fused ----------------
__global__ void cvtw1z_kernel(const float4* __restrict__ s) {
    if (blockIdx.x == 0) {
        if (threadIdx.x < 32 * EE) g_chcnt[threadIdx.x] = 0;
        if (threadIdx.x < EE) g_imp[threadIdx.x] = 0.f;
    }
    const int NT = 1024 * 256;
    int t = blockIdx.x * 256 + threadIdx.x;
#pragma unroll
    for (int k = 0; k < 4; k++) {
        size_t i = (size_t)t + (size_t)k * NT;
        ((uint4*)g_w1h)[i] = pack8h(s[2 * i], s[2 * i + 1]);
    }
}
__global__ void cvtw2_kernel(const float4* __restrict__ s) {
    const int NT = 1024 * 256;
    int t = blockIdx.x * 256 + threadIdx.x;
#pragma unroll
    for (int k = 0; k < 4; k++) {
        size_t i = (size_t)t + (size_t)k * NT;
        ((uint4*)g_w2h)[i] = pack8h(s[2 * i], s[2 * i + 1]);
    }
}

// ---------------- kernel 2: router (float4 MLP, fused fp16-x emit, chunk counts) ----------------
__global__ void __launch_bounds__(256) router_kernel(const float4* __restrict__ x4,
                                                     const float4* __restrict__ gw4) {
    __shared__ float4 sgw[EE * 128];
    __shared__ float  simp[EE];
    int tid = threadIdx.x;
    for (int i = tid; i < EE * 128; i += 256) sgw[i] = gw4[i];
    if (tid < EE) simp[tid] = 0.f;
    __syncthreads();

    int wid = tid >> 5, lane = tid & 31;
    int t = blockIdx.x * 8 + wid;
    const float4* xr = x4 + (size_t)t * 128;

    float4 xv[4];
#pragma unroll
    for (int i = 0; i < 4; i++) xv[i] = xr[lane + 32 * i];

    // emit fp16 copy of x
    uint2* xh = (uint2*)(g_xh + (size_t)t * DD);
#pragma unroll
    for (int i = 0; i < 4; i++) {
        __half2 lo = __floats2half2_rn(xv[i].x, xv[i].y);
        __half2 hi = __floats2half2_rn(xv[i].z, xv[i].w);
        uint2 u;
        u.x = *reinterpret_cast<unsigned*>(&lo);
        u.y = *reinterpret_cast<unsigned*>(&hi);
        xh[lane + 32 * i] = u;
    }

    float acc[EE];
#pragma unroll
    for (int e = 0; e < EE; e++) acc[e] = 0.f;
#pragma unroll
    for (int i = 0; i < 4; i++) {
#pragma unroll
        for (int e = 0; e < EE; e++) {
            float4 w = sgw[e * 128 + lane + 32 * i];
            acc[e] = fmaf(xv[i].x, w.x, fmaf(xv[i].y, w.y,
                     fmaf(xv[i].z, w.z, fmaf(xv[i].w, w.w, acc[e]))));
        }
    }
#pragma unroll
    for (int e = 0; e < EE; e++) {
#pragma unroll
        for (int o = 16; o > 0; o >>= 1)
            acc[e] += __shfl_xor_sync(0xffffffffu, acc[e], o);
    }
    if (lane == 0) {
        float mx = acc[0];
#pragma unroll
        for (int e = 1; e < EE; e++) mx = fmaxf(mx, acc[e]);
        float g[EE], s = 0.f;
#pragma unroll
        for (int e = 0; e < EE; e++) { g[e] = expf(acc[e] - mx); s += g[e]; }
        float inv = 1.f / s;
#pragma unroll
        for (int e = 0; e < EE; e++) { g[e] *= inv; atomicAdd(&simp[e], g[e]); }
        int i0 = 0; float g0 = g[0];
#pragma unroll
        for (int e = 1; e < EE; e++) if (g[e] > g0) { g0 = g[e]; i0 = e; }
        int i1 = -1; float g1 = -1.f;
#pragma unroll
        for (int e = 0; e < EE; e++) if (e != i0 && g[e] > g1) { g1 = g[e]; i1 = e; }
        g_ti[t] = i0;        g_ti[TT + t] = i1;
        g_tg[t] = g0;        g_tg[TT + t] = g1;
        atomicAdd(&g_chcnt[(t >> 8) * EE + i0], 1);             // slot-0 entry j = t
        atomicAdd(&g_chcnt[((TT + t) >> 8) * EE + i1], 1);      // slot-1 entry j = TT+t
    }
    __syncthreads();
    if (tid < EE) atomicAdd(&g_imp[tid], simp[tid]);
}

// ---------------- kernel 3: dispatch (32 blocks x 256; exact slot-major order) ----------------
__global__ void __launch_bounds__(256) dispatch_kernel(float* __restrict__ out, int out_size) {
    __shared__ int scnt[32 * EE];
    __shared__ int wcnt[8][EE];
    int tid = threadIdx.x, lane = tid & 31, w = tid >> 5;
    scnt[tid] = g_chcnt[tid];
    __syncthreads();

    int j = blockIdx.x * 256 + tid;
    int e = g_ti[j];
    unsigned mymask = 0;
#pragma unroll
    for (int q = 0; q < EE; q++) {
        unsigned m = __ballot_sync(0xffffffffu, e == q);
        if (e == q) mymask = m;
        if (lane == q) wcnt[w][q] = __popc(m);
    }
    int lanepos = __popc(mymask & ((1u << lane) - 1u));
    __syncthreads();

    int base = 0;
    for (int c = 0; c < blockIdx.x; c++) base += scnt[c * EE + e];
    int woff = 0;
    for (int ww = 0; ww < w; ww++) woff += wcnt[ww][e];
    int pos = base + woff + lanepos;
    if (pos < CAP) {
        int o = e * CAPMAX + pos;
        g_dtok[o] = j & (TT - 1);
        g_dwt[o]  = g_tg[j];
        g_inv[j]  = o;
    } else {
        g_inv[j] = -1;
    }

    if (blockIdx.x == 0 && tid == 0) {
        float tpe[EE];
        for (int q = 0; q < EE; q++) {
            int tot = 0;
            for (int c = 0; c < 32; c++) tot += scnt[c * EE + q];
            int capped = min(tot, CAP);
            g_cnt[q] = capped;
            tpe[q] = (float)capped;
        }
        double s = 0, ss = 0;
        for (int q = 0; q < EE; q++) { s += tpe[q]; ss += (double)tpe[q] * tpe[q]; }
        double m = s / 8.0, var = ss / 8.0 - m * m; if (var < 0) var = 0;
        double l_load = var / ((m + 1e-6) * (m + 1e-6));
        double s2 = 0, sq2 = 0;
        for (int q = 0; q < EE; q++) { double v = g_imp[q]; s2 += v; sq2 += v * v; }
        double m2 = s2 / 8.0, v2 = sq2 / 8.0 - m2 * m2; if (v2 < 0) v2 = 0;
        double imp_loss = v2 / ((m2 + 1e-6) * (m2 + 1e-6));
        if (out_size >= TT * DD + 2) {
            out[TT * DD]     = (float)(0.5 * (imp_loss + l_load));
            out[TT * DD + 1] = (float)l_load;
        }
    }
}

// ============ fp16 GEMM tiling ============
// Block tile 128x128, 4 warps (2x2), warp tile 64x64, k-slab 32, 4-stage cp.async.
#define A_LDH 40
#define B_LDH 136
#define STG_B 18944
#define OFF_CTRL 18944               // floats (= 75776 B)
#define GSMEM_BYTES ((OFF_CTRL + 384) * 4)

// ---------------- kernel 4: GEMM1  hbuf(fp16) = wt * gelu(Xg @ W1[e] + b1[e]) ----------------
__global__ void __launch_bounds__(128, 2) gemm1_kernel(const float* __restrict__ b1) {
    extern __shared__ float sm[];
    unsigned int smb = (unsigned int)__cvta_generic_to_shared(sm);
    int*   toks = (int*)(sm + OFF_CTRL);
    float* swt  = sm + OFF_CTRL + 128;
    float* bis  = sm + OFF_CTRL + 256;

    int e = blockIdx.z;
    int rows = g_cnt[e];
    int row0 = blockIdx.x * 128;
    if (row0 >= rows) return;
    int h0 = blockIdx.y * 128;

    int tid = threadIdx.x;
    {
        int r = row0 + tid;
        toks[tid] = (r < rows) ? g_dtok[e * CAPMAX + r] : -1;
        swt[tid]  = (r < rows) ? g_dwt[e * CAPMAX + r] : 0.f;
        bis[tid]  = b1[e * HH + h0 + tid];
    }
    __syncthreads();

    const __half* w1e = g_w1h + (size_t)e * DD * HH;

    auto fill = [&](int s) {
        int k0 = s * 32;
        unsigned int Ad = smb + (unsigned int)((s & 3) * STG_B);
        unsigned int Bd = Ad + 10240u;
#pragma unroll
        for (int it = 0; it < 4; it++) {
            int idx = tid + it * 128;
            int r = idx >> 2, c = idx & 3;
            int tok = toks[r];
            cp16(Ad + (unsigned int)(r * 80 + c * 16),
                 g_xh + (size_t)(tok < 0 ? 0 : tok) * DD + k0 + c * 8, tok < 0 ? 0 : 16);
        }
#pragma unroll
        for (int it = 0; it < 4; it++) {
            int idx = tid + it * 128;
            int kr = idx >> 4, c = idx & 15;
            cp16(Bd + (unsigned int)(kr * 272 + c * 16),
                 w1e + (size_t)(k0 + kr) * HH + h0 + c * 8, 16);
        }
    };

    fill(0); cp_commit();
    fill(1); cp_commit();
    fill(2); cp_commit();

    int wid = tid >> 5, wm = wid & 1, wn = wid >> 1;   // warp tile 64x64
    wmma::fragment<wmma::accumulator, 16, 16, 16, float> acc[4][4];
#pragma unroll
    for (int mi = 0; mi < 4; mi++)
#pragma unroll
        for (int ni = 0; ni < 4; ni++) wmma::fill_fragment(acc[mi][ni], 0.f);

    const int KS = DD / 32;   // 16
    for (int ks = 0; ks < KS; ks++) {
        cp_wait<2>();
        __syncthreads();
        if (ks + 3 < KS) fill(ks + 3);
        cp_commit();
        const __half* Ab = (const __half*)sm + (size_t)(ks & 3) * (STG_B / 2);
        const __half* Bb = Ab + 5120;
#pragma unroll
        for (int kk = 0; kk < 2; kk++) {
            wmma::fragment<wmma::matrix_a, 16, 16, 16, __half, wmma::row_major> a[4];
            wmma::fragment<wmma::matrix_b, 16, 16, 16, __half, wmma::row_major> b[4];
#pragma unroll
            for (int mi = 0; mi < 4; mi++)
                wmma::load_matrix_sync(a[mi], Ab + (wm * 64 + mi * 16) * A_LDH + kk * 16, A_LDH);
#pragma unroll
            for (int ni = 0; ni < 4; ni++)
                wmma::load_matrix_sync(b[ni], Bb + (kk * 16) * B_LDH + wn * 64 + ni * 16, B_LDH);
#pragma unroll
            for (int mi = 0; mi < 4; mi++)
#pragma unroll
                for (int ni = 0; ni < 4; ni++)
                    wmma::mma_sync(acc[mi][ni], a[mi], b[ni], acc[mi][ni]);
        }
    }

    __syncthreads();
    float* Cs = sm;   // [128][136] fp32
#pragma unroll
    for (int mi = 0; mi < 4; mi++)
#pragma unroll
        for (int ni = 0; ni < 4; ni++)
            wmma::store_matrix_sync(Cs + (size_t)(wm * 64 + mi * 16) * 136 + wn * 64 + ni * 16,
                                    acc[mi][ni], 136, wmma::mem_row_major);
    __syncthreads();
    __half* hb = g_hbuf + (size_t)(e * CAPMAX + row0) * HH + h0;
#pragma unroll
    for (int i = 0; i < 64; i++) {
        int idx = tid + i * 128;
        int r = idx >> 6, c2 = idx & 63;
        float w = swt[r];
        float v0 = gelu_f(Cs[r * 136 + 2 * c2]     + bis[2 * c2])     * w;
        float v1 = gelu_f(Cs[r * 136 + 2 * c2 + 1] + bis[2 * c2 + 1]) * w;
        ((__half2*)(hb + (size_t)r * HH))[c2] = __floats2half2_rn(v0, v1);
    }
}

// ---------------- kernel 5: GEMM2  ybuf = hbuf @ W2[e] + wt*b2 ----------------
__global__ void __launch_bounds__(128, 2) gemm2_kernel(const float* __restrict__ b2) {
    extern __shared__ float sm[];
    unsigned int smb = (unsigned int)__cvta_generic_to_shared(sm);
    float* swt = sm + OFF_CTRL + 128;
    float* bis = sm + OFF_CTRL + 256;

    int e = blockIdx.z;
    int rows = g_cnt[e];
    int row0 = blockIdx.x * 128;
    if (row0 >= rows) return;
    int d0 = blockIdx.y * 128;

    int tid = threadIdx.x;
    {
        int r = row0 + tid;
        swt[tid] = (r < rows) ? g_dwt[e * CAPMAX + r] : 0.f;
        bis[tid] = b2[e * DD + d0 + tid];
    }
    __syncthreads();

    const __half* hbase = g_hbuf + (size_t)(e * CAPMAX + row0) * HH;
    const __half* w2e = g_w2h + (size_t)e * HH * DD;

    auto fill = [&](int s) {
        int k0 = s * 32;
        unsigned int Ad = smb + (unsigned int)((s & 3) * STG_B);
        unsigned int Bd = Ad + 10240u;
#pragma unroll
        for (int it = 0; it < 4; it++) {
            int idx = tid + it * 128;
            int r = idx >> 2, c = idx & 3;
            cp16(Ad + (unsigned int)(r * 80 + c * 16),
                 hbase + (size_t)r * HH + k0 + c * 8, 16);
        }
#pragma unroll
        for (int it = 0; it < 4; it++) {
            int idx = tid + it * 128;
            int kr = idx >> 4, c = idx & 15;
            cp16(Bd + (unsigned int)(kr * 272 + c * 16),
                 w2e + (size_t)(k0 + kr) * DD + d0 + c * 8, 16);
        }
    };

    fill(0); cp_commit();
    fill(1); cp_commit();
    fill(2); cp_commit();

    int wid = tid >> 5, wm = wid & 1, wn = wid >> 1;
    wmma::fragment<wmma::accumulator, 16, 16, 16, float> acc[4][4];
#pragma unroll
    for (int mi = 0; mi < 4; mi++)
#pragma unroll
        for (int ni = 0; ni < 4; ni++) wmma::fill_fragment(acc[mi][ni], 0.f);

    const int KS = HH / 32;   // 64
    for (int ks = 0; ks < KS; ks++) {
        cp_wait<2>();
        __syncthreads();
        if (ks + 3 < KS) fill(ks + 3);
        cp_commit();
        const __half* Ab = (const __half*)sm + (size_t)(ks & 3) * (STG_B / 2);
        const __half* Bb = Ab + 5120;
#pragma unroll
        for (int kk = 0; kk < 2; kk++) {
            wmma::fragment<wmma::matrix_a, 16, 16, 16, __half, wmma::row_major> a[4];
            wmma::fragment<wmma::matrix_b, 16, 16, 16, __half, wmma::row_major> b[4];
#pragma unroll
            for (int mi = 0; mi < 4; mi++)
                wmma::load_matrix_sync(a[mi], Ab + (wm * 64 + mi * 16) * A_LDH + kk * 16, A_LDH);
#pragma unroll
            for (int ni = 0; ni < 4; ni++)
                wmma::load_matrix_sync(b[ni], Bb + (kk * 16) * B_LDH + wn * 64 + ni * 16, B_LDH);
#pragma unroll
            for (int mi = 0; mi < 4; mi++)
#pragma unroll
                for (int ni = 0; ni < 4; ni++)
                    wmma::mma_sync(acc[mi][ni], a[mi], b[ni], acc[mi][ni]);
        }
    }

    __syncthreads();
    float* Cs = sm;
#pragma unroll
    for (int mi = 0; mi < 4; mi++)
#pragma unroll
        for (int ni = 0; ni < 4; ni++)
            wmma::store_matrix_sync(Cs + (size_t)(wm * 64 + mi * 16) * 136 + wn * 64 + ni * 16,
                                    acc[mi][ni], 136, wmma::mem_row_major);
    __syncthreads();
    float* yb = g_ybuf + (size_t)(e * CAPMAX + row0) * DD + d0;
#pragma unroll
    for (int i = 0; i < 128; i++) {
        int idx = tid + i * 128;
        int r = idx >> 7, c = idx & 127;
        yb[(size_t)r * DD + c] = Cs[r * 136 + c] + swt[r] * bis[c];
    }
}

// ---------------- kernel 6: gather-combine ----------------
__global__ void __launch_bounds__(256) combine_kernel(float* __restrict__ out) {
    int i = blockIdx.x * 256 + threadIdx.x;
    int t = i >> 7;
    int d = i & 127;
    int i0 = g_inv[t], i1 = g_inv[TT + t];
    float4 a = make_float4(0.f, 0.f, 0.f, 0.f), b = a;
    if (i0 >= 0) a = *((const float4*)g_ybuf + (size_t)i0 * 128 + d);
    if (i1 >= 0) b = *((const float4*)g_ybuf + (size_t)i1 * 128 + d);
    ((float4*)out)[i] = make_float4(a.x + b.x, a.y + b.y, a.z + b.z, a.w + b.w);
}

// ---------------- launch ----------------
extern "C" void kernel_launch(void* const* d_in, const int* in_sizes, int n_in,
                              void* d_out, int out_size) {
    const float* x  = (const float*)d_in[0];
    const float* gw = (const float*)d_in[1];
    const float* w1 = (const float*)d_in[2];
    const float* b1 = (const float*)d_in[3];
    const float* w2 = (const float*)d_in[4];
    const float* b2 = (const float*)d_in[5];
    float* out = (float*)d_out;

    cudaFuncSetAttribute(gemm1_kernel, cudaFuncAttributeMaxDynamicSharedMemorySize, GSMEM_BYTES);
    cudaFuncSetAttribute(gemm2_kernel, cudaFuncAttributeMaxDynamicSharedMemorySize, GSMEM_BYTES);

    // gemm1 is the 4th launch (ncu profiles the 4th)
    cvtw1z_kernel<<<1024, 256>>>((const float4*)w1);
    router_kernel<<<TT / 8, 256>>>((const float4*)x, (const float4*)gw);
    dispatch_kernel<<<32, 256>>>(out, out_size);
    gemm1_kernel<<<dim3(CAPMAX / 128, HH / 128, EE), 128, GSMEM_BYTES>>>(b1);
    cvtw2_kernel<<<1024, 256>>>((const float4*)w2);
    gemm2_kernel<<<dim3(CAPMAX / 128, DD / 128, EE), 128, GSMEM_BYTES>>>(b2);
    combine_kernel<<<(TT * DD / 4) / 256, 256>>>(out);
}